// round 12
// baseline (speedup 1.0000x reference)
#include <cuda_runtime.h>
#include <cuda_bf16.h>
#include <math.h>
#include <stdint.h>

#define SQ 1024
#define DMODEL 1024

// ---------------- scratch (static device globals; allocation-free) -------------
__device__ __nv_bfloat16 c_bf  [(size_t)8192*1024];   // concat(memory,x), row n=t*4+b
__device__ __nv_bfloat16 pos_bf[(size_t)2048*1024];
__device__ __nv_bfloat16 wqkvT [(size_t)3072*1024];   // W_qkv^T
__device__ __nv_bfloat16 wrelT [(size_t)1024*1024];
__device__ __nv_bfloat16 woT   [(size_t)1024*1024];
__device__ __nv_bfloat16 g_qu  [(size_t)64*1024*64];  // [bh][i][dh]
__device__ __nv_bfloat16 g_qv  [(size_t)64*1024*64];
__device__ __nv_bfloat16 g_k   [(size_t)64*2048*64];  // [bh][t][dh]
__device__ __nv_bfloat16 g_vT  [(size_t)64*64*2048];  // [bh][dh][t]
__device__ __nv_bfloat16 g_r   [(size_t)16*2048*64];  // [h][p][dh]
__device__ __nv_bfloat16 g_BDs [(size_t)64*1024*2048];// pre-SHIFTED BD, [bh][i][j] bf16
__device__ __nv_bfloat16 g_avec[(size_t)4096*1024];   // [i*4+b][h*64+dh]
__device__ float         g_aout[(size_t)4096*1024];

// ---------------- helpers -------------------------------------------------------
__device__ __forceinline__ uint32_t smem_u32(const void* p){
    uint32_t a;
    asm("{ .reg .u64 t; cvta.to.shared.u64 t, %1; cvt.u32.u64 %0, t; }" : "=r"(a) : "l"(p));
    return a;
}
__device__ __forceinline__ uint32_t pk2(float a, float b){
    return (uint32_t)__bfloat16_as_ushort(__float2bfloat16(a))
         | ((uint32_t)__bfloat16_as_ushort(__float2bfloat16(b)) << 16);
}
__device__ __forceinline__ float lo_bf(uint32_t u){
    return __bfloat162float(__ushort_as_bfloat16((unsigned short)(u & 0xffffu)));
}
__device__ __forceinline__ float hi_bf(uint32_t u){
    return __bfloat162float(__ushort_as_bfloat16((unsigned short)(u >> 16)));
}
__device__ __forceinline__ void ldm_x4(uint32_t* r, uint32_t addr){
    asm volatile("ldmatrix.sync.aligned.m8n8.x4.shared.b16 {%0,%1,%2,%3}, [%4];"
        : "=r"(r[0]), "=r"(r[1]), "=r"(r[2]), "=r"(r[3]) : "r"(addr));
}
__device__ __forceinline__ void mma16816(float* c, const uint32_t* a, const uint32_t* b){
    asm volatile("mma.sync.aligned.m16n8k16.row.col.f32.bf16.bf16.f32 "
        "{%0,%1,%2,%3}, {%4,%5,%6,%7}, {%8,%9}, {%0,%1,%2,%3};"
        : "+f"(c[0]), "+f"(c[1]), "+f"(c[2]), "+f"(c[3])
        : "r"(a[0]), "r"(a[1]), "r"(a[2]), "r"(a[3]), "r"(b[0]), "r"(b[1]));
}
__device__ __forceinline__ void cpa16(uint32_t dst, const void* src){
    asm volatile("cp.async.cg.shared.global [%0], [%1], 16;" :: "r"(dst), "l"(src));
}
#define CPA_COMMIT() asm volatile("cp.async.commit_group;" ::: "memory")
#define CPA_WAIT0()  asm volatile("cp.async.wait_group 0;" ::: "memory")

// ---------------- prep kernels --------------------------------------------------
__global__ void __launch_bounds__(256) conv_c(const float* __restrict__ mem, const float* __restrict__ x){
    size_t n = blockIdx.x;
    const float* src = (n < 4096) ? (mem + n*1024) : (x + (n-4096)*1024);
    __nv_bfloat16* dst = c_bf + n*1024;
#pragma unroll
    for (int q = 0; q < 4; q++){ int d = threadIdx.x + q*256; dst[d] = __float2bfloat16(src[d]); }
}
__global__ void __launch_bounds__(256) conv_pos(const float* __restrict__ pe){
    size_t n = blockIdx.x;
    const float* src = pe + n*1024;
    __nv_bfloat16* dst = pos_bf + n*1024;
#pragma unroll
    for (int q = 0; q < 4; q++){ int d = threadIdx.x + q*256; dst[d] = __float2bfloat16(src[d]); }
}
// transpose fp32 [1024][C] -> bf16 [C][1024]
__global__ void __launch_bounds__(256) transpose_bf(const float* __restrict__ src, int mode, int C){
    __shared__ float tile[32][33];
    __nv_bfloat16* dst = (mode == 0) ? wqkvT : (mode == 1) ? wrelT : woT;
    const int R = 1024;
    int c0 = blockIdx.x*32, r0 = blockIdx.y*32;
    int tx = threadIdx.x & 31, ty = threadIdx.x >> 5;
#pragma unroll
    for (int q = 0; q < 4; q++)
        tile[ty + q*8][tx] = src[(size_t)(r0 + ty + q*8)*C + c0 + tx];
    __syncthreads();
#pragma unroll
    for (int q = 0; q < 4; q++)
        dst[(size_t)(c0 + ty + q*8)*R + r0 + tx] = __float2bfloat16(tile[tx][ty + q*8]);
}

// ---------------- generic mma.sync GEMM, cp.async double-buffered ----------------
// MODE 0: QKV   c_bf(8192x1024) @ wqkvT^T  -> scatter qu/qv/k/vT (bf16)
// MODE 1: REL   pos_bf(2048x1024) @ wrelT^T -> g_r (bf16)
// MODE 3: BD    qv(1024x64) @ r^T(2048x64) per bh -> pre-shifted bf16 g_BDs
// MODE 5: OUT   avec(4096x1024) @ woT^T   -> g_aout (f32)
template<int MODE>
__global__ void __launch_bounds__(256) gemm_tc(const float* __restrict__ bu, const float* __restrict__ bv)
{
    constexpr int KC = (MODE == 3) ? 64 : 128;
    constexpr int NT = 128;
    constexpr int NF = NT / 32;
    constexpr int SA = KC*2 + 16;
    constexpr int ASZ = 128*SA;
    constexpr int BSZ = NT*SA;
    constexpr int BUFSZ = ASZ + BSZ;
    extern __shared__ char smem[];
    float* stage = (float*)smem;                 // aliases buffers; used after mainloop
    const uint32_t sm32 = smem_u32(smem);

    const int tid = threadIdx.x;
    const int lane = tid & 31, wid = tid >> 5;
    const int wm = wid & 1, wn = wid >> 1;

    int m0, n0, bh = 0, h = 0, nchunks;
    if (MODE == 0)      { m0 = blockIdx.y*128; n0 = blockIdx.x*128; nchunks = 8; }
    else if (MODE == 1) { m0 = blockIdx.y*128; n0 = blockIdx.x*128; nchunks = 8; }
    else if (MODE == 3) { bh = blockIdx.z; h = bh & 15; m0 = blockIdx.y*128; n0 = blockIdx.x*128;
                          if (n0 + m0 <= 768) return; nchunks = 1; }
    else                { m0 = blockIdx.y*128; n0 = blockIdx.x*128; nchunks = 8; }

    constexpr int RQ = KC/8;
    constexpr int APT = 128*RQ/256;
    constexpr int BPT = NT*RQ/256;

    auto load_chunk = [&](int ch, int buf){
        const int k0 = ch * KC;
        const uint32_t baseA = sm32 + buf*BUFSZ;
        const uint32_t baseB = baseA + ASZ;
#pragma unroll
        for (int qq = 0; qq < APT; qq++) {
            int idx = qq*256 + tid;
            int row = idx / RQ, q = idx % RQ;
            const __nv_bfloat16* ap;
            if      (MODE == 0) ap = c_bf   + (size_t)(m0+row)*1024 + k0;
            else if (MODE == 1) ap = pos_bf + (size_t)(m0+row)*1024 + k0;
            else if (MODE == 3) ap = g_qv + ((size_t)bh*1024 + m0+row)*64 + k0;
            else                ap = g_avec + (size_t)(m0+row)*1024 + k0;
            cpa16(baseA + row*SA + q*16, ap + q*8);
        }
#pragma unroll
        for (int qq = 0; qq < BPT; qq++) {
            int idx = qq*256 + tid;
            int row = idx / RQ, q = idx % RQ;
            const __nv_bfloat16* bp;
            if      (MODE == 0) bp = wqkvT + (size_t)(n0+row)*1024 + k0;
            else if (MODE == 1) bp = wrelT + (size_t)(n0+row)*1024 + k0;
            else if (MODE == 3) bp = g_r + ((size_t)h*2048 + n0+row)*64 + k0;
            else                bp = woT + (size_t)(n0+row)*1024 + k0;
            cpa16(baseB + row*SA + q*16, bp + q*8);
        }
        CPA_COMMIT();
    };

    float acc[4][NF][4] = {};

    int buf = 0;
    load_chunk(0, 0);
    CPA_WAIT0();
    __syncthreads();

    for (int ch = 0; ch < nchunks; ch++) {
        if (ch + 1 < nchunks) load_chunk(ch + 1, buf ^ 1);
        const uint32_t smA32 = sm32 + buf*BUFSZ;
        const uint32_t smB32 = smA32 + ASZ;
#pragma unroll
        for (int ks = 0; ks < KC/16; ks++) {
            const int colb = ks*32 + (lane >> 4)*16;
            uint32_t af[4][4];
#pragma unroll
            for (int mf = 0; mf < 4; mf++) {
                int r = wm*64 + mf*16 + (lane & 15);
                ldm_x4(af[mf], smA32 + r*SA + colb);
            }
            uint32_t bfr[NF][2];
#pragma unroll
            for (int nf2 = 0; nf2 < NF/2; nf2++) {
                uint32_t t4[4];
                int r = wn*(NT/4) + nf2*16 + (lane & 15);
                ldm_x4(t4, smB32 + r*SA + colb);
                bfr[2*nf2][0]   = t4[0]; bfr[2*nf2][1]   = t4[2];
                bfr[2*nf2+1][0] = t4[1]; bfr[2*nf2+1][1] = t4[3];
            }
#pragma unroll
            for (int mf = 0; mf < 4; mf++)
#pragma unroll
                for (int nf = 0; nf < NF; nf++)
                    mma16816(acc[mf][nf], af[mf], bfr[nf]);
        }
        CPA_WAIT0();
        __syncthreads();
        buf ^= 1;
    }

    // ---- dump fragments to staged SMEM [128][NT+1] (aliases buffers) ----
#pragma unroll
    for (int mf = 0; mf < 4; mf++)
#pragma unroll
        for (int nf = 0; nf < NF; nf++) {
            int r0 = wm*64 + mf*16 + (lane >> 2);
            int c0 = wn*(NT/4) + nf*8 + (lane & 3)*2;
            stage[r0*(NT+1)+c0]       = acc[mf][nf][0];
            stage[r0*(NT+1)+c0+1]     = acc[mf][nf][1];
            stage[(r0+8)*(NT+1)+c0]   = acc[mf][nf][2];
            stage[(r0+8)*(NT+1)+c0+1] = acc[mf][nf][3];
        }
    __syncthreads();
    if (tid >= 128) return;

#define STG(r,c) stage[(r)*(NT+1)+(c)]

    if (MODE == 0) {
#pragma unroll
        for (int g = 0; g < 4; g++) {
            const int gc0 = n0 + g*32;
            const int which = gc0 >> 10;
            const int hc0 = gc0 & 1023;
            const int hh = hc0 >> 6, dh0 = hc0 & 63;
            const int n = m0 + tid, t = n >> 2, bb = n & 3;
            if (which == 0) {
                if (t >= 1024) {
                    uint32_t pu[16], pv[16];
#pragma unroll
                    for (int c = 0; c < 32; c += 2) {
                        float v0 = STG(tid, g*32+c), v1 = STG(tid, g*32+c+1);
                        pu[c>>1] = pk2(v0 + bu[hc0+c], v1 + bu[hc0+c+1]);
                        pv[c>>1] = pk2(v0 + bv[hc0+c], v1 + bv[hc0+c+1]);
                    }
                    size_t base = ((size_t)(bb*16+hh)*1024 + (t-1024))*64 + dh0;
#pragma unroll
                    for (int q = 0; q < 4; q++) {
                        *(uint4*)(g_qu + base + q*8) = make_uint4(pu[q*4], pu[q*4+1], pu[q*4+2], pu[q*4+3]);
                        *(uint4*)(g_qv + base + q*8) = make_uint4(pv[q*4], pv[q*4+1], pv[q*4+2], pv[q*4+3]);
                    }
                }
            } else if (which == 1) {
                uint32_t pk[16];
#pragma unroll
                for (int c = 0; c < 32; c += 2) pk[c>>1] = pk2(STG(tid, g*32+c), STG(tid, g*32+c+1));
                size_t base = ((size_t)(bb*16+hh)*2048 + t)*64 + dh0;
#pragma unroll
                for (int q = 0; q < 4; q++)
                    *(uint4*)(g_k + base + q*8) = make_uint4(pk[q*4], pk[q*4+1], pk[q*4+2], pk[q*4+3]);
            } else {
                const int c2 = tid & 31, sub = tid >> 5;
                const int t0 = m0 >> 2;
                uint32_t w[16];
#pragma unroll
                for (int tl = 0; tl < 32; tl += 2)
                    w[tl>>1] = pk2(STG(tl*4+sub, g*32+c2), STG((tl+1)*4+sub, g*32+c2));
                size_t base = ((size_t)(sub*16+hh)*64 + dh0 + c2)*2048 + t0;
#pragma unroll
                for (int q = 0; q < 4; q++)
                    *(uint4*)(g_vT + base + q*8) = make_uint4(w[q*4], w[q*4+1], w[q*4+2], w[q*4+3]);
            }
        }
    } else if (MODE == 1) {
#pragma unroll
        for (int g = 0; g < 4; g++) {
            const int gc0 = n0 + g*32;
            const int hh = gc0 >> 6, dh0 = gc0 & 63;
            uint32_t pk[16];
#pragma unroll
            for (int c = 0; c < 32; c += 2) pk[c>>1] = pk2(STG(tid, g*32+c), STG(tid, g*32+c+1));
            size_t base = ((size_t)hh*2048 + (m0+tid))*64 + dh0;
#pragma unroll
            for (int q = 0; q < 4; q++)
                *(uint4*)(g_r + base + q*8) = make_uint4(pk[q*4], pk[q*4+1], pk[q*4+2], pk[q*4+3]);
        }
    } else if (MODE == 3) {
        // pre-shifted BD store: g_BDs[bh][i][j] = BD[i][p], j = p + i - 1023
        const int i = m0 + tid;
        __nv_bfloat16* dst = g_BDs + ((size_t)bh*1024 + i)*2048;
#pragma unroll
        for (int g = 0; g < 4; g++) {
            const int gc0 = n0 + g*32;
            const int jbase = gc0 + i - 1023;
            float v[32];
#pragma unroll
            for (int c = 0; c < 32; c++) v[c] = STG(tid, g*32+c);
            if (!(jbase & 1)) {
#pragma unroll
                for (int c = 0; c < 32; c += 2) {
                    int j = jbase + c;
                    if (j >= 0) *(uint32_t*)(dst + j) = pk2(v[c], v[c+1]);
                }
            } else {
                if (jbase >= 0) dst[jbase] = __float2bfloat16(v[0]);
#pragma unroll
                for (int c = 1; c < 31; c += 2) {
                    int j = jbase + c;
                    if (j >= 0) *(uint32_t*)(dst + j) = pk2(v[c], v[c+1]);
                }
                if (jbase + 31 >= 0) dst[jbase + 31] = __float2bfloat16(v[31]);
            }
        }
    } else {
        float* dst = g_aout + (size_t)(m0+tid)*1024;
#pragma unroll
        for (int g = 0; g < 4; g++) {
            const int gc0 = n0 + g*32;
#pragma unroll
            for (int c = 0; c < 32; c += 4)
                *(float4*)(dst + gc0 + c) = make_float4(STG(tid, g*32+c),   STG(tid, g*32+c+1),
                                                        STG(tid, g*32+c+2), STG(tid, g*32+c+3));
        }
    }
#undef STG
}

// ---------------- fused flash attention, cp.async double-buffered K/V ------------
// grid (8 i-tiles, 64 bh), 256 threads. Warp w owns query rows [16w, 16w+16).
#define FK_SZ (128*144)
#define FV_SZ (64*272)
#define FSMEM (2*FK_SZ + 2*FV_SZ)
__global__ void __launch_bounds__(256, 1) flash_attn()
{
    extern __shared__ char fsm[];
    const uint32_t sm32 = smem_u32(fsm);

    const int bh = blockIdx.y, b = bh >> 4, h = bh & 15;
    const int m0 = (7 - blockIdx.x) * 128;        // longest-work-first
    const int tid = threadIdx.x, lane = tid & 31, w = tid >> 5;
    const int r0 = w * 16;

    // ---- qu tile -> smem(K0) -> A fragments (held in regs for all j-tiles) ----
    {
        const __nv_bfloat16* qp = g_qu + ((size_t)bh*1024 + m0)*64;
#pragma unroll
        for (int q4 = 0; q4 < 4; q4++) {
            int idx = q4*256 + tid; int row = idx >> 3, q = idx & 7;
            *(uint4*)(fsm + row*144 + q*16) = *(const uint4*)(qp + (size_t)row*64 + q*8);
        }
    }
    __syncthreads();
    uint32_t af[4][4];
#pragma unroll
    for (int ks = 0; ks < 4; ks++)
        ldm_x4(af[ks], sm32 + (r0 + (lane & 15))*144 + ks*32 + (lane >> 4)*16);
    __syncthreads();

    auto load_kv = [&](int jt, int buf){
        const int j0 = jt * 128;
        const uint32_t kb = sm32 + buf*FK_SZ;
        const uint32_t vb = sm32 + 2*FK_SZ + buf*FV_SZ;
        const __nv_bfloat16* kp = g_k + ((size_t)bh*2048 + j0)*64;
#pragma unroll
        for (int q4 = 0; q4 < 4; q4++) {
            int idx = q4*256 + tid; int row = idx >> 3, q = idx & 7;
            cpa16(kb + row*144 + q*16, kp + (size_t)row*64 + q*8);
        }
        const __nv_bfloat16* vp = g_vT + ((size_t)bh*64)*2048 + j0;
#pragma unroll
        for (int q4 = 0; q4 < 4; q4++) {
            int idx = q4*256 + tid; int row = idx >> 4, q = idx & 15;
            cpa16(vb + row*272 + q*16, vp + (size_t)row*2048 + q*8);
        }
        CPA_COMMIT();
    };

    float mrow0 = -1e30f, mrow1 = -1e30f, lrow0 = 0.f, lrow1 = 0.f;
    float oacc[8][4] = {};
    const int ia = m0 + r0 + (lane >> 2);         // row A; row B = ia + 8
    const uint32_t* bdr0 = (const uint32_t*)(g_BDs + ((size_t)bh*1024 + ia)*2048);
    const uint32_t* bdr1 = (const uint32_t*)(g_BDs + ((size_t)bh*1024 + ia + 8)*2048);

    const int ntiles = m0/128 + 9;
    int buf = 0;
    load_kv(0, 0);
    CPA_WAIT0();
    __syncthreads();

    for (int jt = 0; jt < ntiles; jt++) {
        const int j0 = jt * 128;
        if (jt + 1 < ntiles) load_kv(jt + 1, buf ^ 1);
        const uint32_t smK32 = sm32 + buf*FK_SZ;
        const uint32_t smV32 = sm32 + 2*FK_SZ + buf*FV_SZ;

        // ---- S = qu * K^T  (16 rows x 128 cols per warp) ----
        float sacc[16][4] = {};
#pragma unroll
        for (int ks = 0; ks < 4; ks++) {
            uint32_t bfrg[16][2];
#pragma unroll
            for (int nb = 0; nb < 8; nb++) {
                uint32_t t4[4];
                ldm_x4(t4, smK32 + (nb*16 + (lane & 15))*144 + ks*32 + (lane >> 4)*16);
                bfrg[2*nb][0]   = t4[0]; bfrg[2*nb][1]   = t4[2];
                bfrg[2*nb+1][0] = t4[1]; bfrg[2*nb+1][1] = t4[3];
            }
#pragma unroll
            for (int nf = 0; nf < 16; nf++) mma16816(sacc[nf], af[ks], bfrg[nf]);
        }

        // ---- logits: + shifted BD, * scale, causal mask (predicated select) ----
        float tmax0 = -1e30f, tmax1 = -1e30f;
#pragma unroll
        for (int nf = 0; nf < 16; nf++) {
            int j = j0 + nf*8 + (lane & 3)*2;
            uint32_t bdA = bdr0[j >> 1];
            uint32_t bdB = bdr1[j >> 1];
            float a0 = (sacc[nf][0] + lo_bf(bdA)) * 0.125f;
            float a1 = (sacc[nf][1] + hi_bf(bdA)) * 0.125f;
            float b0 = (sacc[nf][2] + lo_bf(bdB)) * 0.125f;
            float b1 = (sacc[nf][3] + hi_bf(bdB)) * 0.125f;
            sacc[nf][0] = (j     <= ia + 1024)     ? a0 : -1e30f;
            sacc[nf][1] = (j + 1 <= ia + 1024)     ? a1 : -1e30f;
            sacc[nf][2] = (j     <= ia + 8 + 1024) ? b0 : -1e30f;
            sacc[nf][3] = (j + 1 <= ia + 8 + 1024) ? b1 : -1e30f;
            tmax0 = fmaxf(tmax0, fmaxf(sacc[nf][0], sacc[nf][1]));
            tmax1 = fmaxf(tmax1, fmaxf(sacc[nf][2], sacc[nf][3]));
        }
        tmax0 = fmaxf(tmax0, __shfl_xor_sync(0xffffffffu, tmax0, 1));
        tmax0 = fmaxf(tmax0, __shfl_xor_sync(0xffffffffu, tmax0, 2));
        tmax1 = fmaxf(tmax1, __shfl_xor_sync(0xffffffffu, tmax1, 1));
        tmax1 = fmaxf(tmax1, __shfl_xor_sync(0xffffffffu, tmax1, 2));

        const float mnew0 = fmaxf(mrow0, tmax0), mnew1 = fmaxf(mrow1, tmax1);
        const float f0 = __expf(mrow0 - mnew0), f1 = __expf(mrow1 - mnew1);
        mrow0 = mnew0; mrow1 = mnew1;
        lrow0 *= f0; lrow1 *= f1;
#pragma unroll
        for (int nf = 0; nf < 8; nf++) {
            oacc[nf][0] *= f0; oacc[nf][1] *= f0;
            oacc[nf][2] *= f1; oacc[nf][3] *= f1;
        }

        // ---- P = exp(S - m), pack acc frags -> A frags ----
        uint32_t pf[8][4];
        float s0 = 0.f, s1 = 0.f;
#pragma unroll
        for (int kf = 0; kf < 8; kf++) {
            float e00 = __expf(sacc[2*kf][0]   - mnew0), e01 = __expf(sacc[2*kf][1]   - mnew0);
            float e02 = __expf(sacc[2*kf][2]   - mnew1), e03 = __expf(sacc[2*kf][3]   - mnew1);
            float e10 = __expf(sacc[2*kf+1][0] - mnew0), e11 = __expf(sacc[2*kf+1][1] - mnew0);
            float e12 = __expf(sacc[2*kf+1][2] - mnew1), e13 = __expf(sacc[2*kf+1][3] - mnew1);
            s0 += e00 + e01 + e10 + e11;
            s1 += e02 + e03 + e12 + e13;
            pf[kf][0] = pk2(e00, e01);
            pf[kf][1] = pk2(e02, e03);
            pf[kf][2] = pk2(e10, e11);
            pf[kf][3] = pk2(e12, e13);
        }
        lrow0 += s0; lrow1 += s1;

        // ---- O += P * V ----
#pragma unroll
        for (int kf = 0; kf < 8; kf++) {
            uint32_t bv[8][2];
#pragma unroll
            for (int nb = 0; nb < 4; nb++) {
                uint32_t t4[4];
                ldm_x4(t4, smV32 + (nb*16 + (lane & 15))*272 + kf*32 + (lane >> 4)*16);
                bv[2*nb][0]   = t4[0]; bv[2*nb][1]   = t4[2];
                bv[2*nb+1][0] = t4[1]; bv[2*nb+1][1] = t4[3];
            }
#pragma unroll
            for (int nf = 0; nf < 8; nf++) mma16816(oacc[nf], pf[kf], bv[nf]);
        }

        CPA_WAIT0();
        __syncthreads();
        buf ^= 1;
    }

    // ---- finalize: O /= l, write bf16 to g_avec ----
    lrow0 += __shfl_xor_sync(0xffffffffu, lrow0, 1);
    lrow0 += __shfl_xor_sync(0xffffffffu, lrow0, 2);
    lrow1 += __shfl_xor_sync(0xffffffffu, lrow1, 1);
    lrow1 += __shfl_xor_sync(0xffffffffu, lrow1, 2);
    const float inv0 = 1.f / lrow0, inv1 = 1.f / lrow1;

    __nv_bfloat16* d0 = g_avec + ((size_t)ia*4 + b)*1024 + h*64;
    __nv_bfloat16* d1 = g_avec + ((size_t)(ia+8)*4 + b)*1024 + h*64;
#pragma unroll
    for (int nf = 0; nf < 8; nf++) {
        int c = nf*8 + (lane & 3)*2;
        *(uint32_t*)(d0 + c) = pk2(oacc[nf][0]*inv0, oacc[nf][1]*inv0);
        *(uint32_t*)(d1 + c) = pk2(oacc[nf][2]*inv1, oacc[nf][3]*inv1);
    }
}

// ---------------- residual + LayerNorm ------------------------------------------
__global__ void __launch_bounds__(256) ln_kernel(
    const float* __restrict__ x, const float* __restrict__ gamma,
    const float* __restrict__ beta, float* __restrict__ out)
{
    __shared__ float shs[8], shss[8];
    const int n = blockIdx.x;
    const int tid = threadIdx.x;
    const float* xr = x + (size_t)n * DMODEL;
    const float* ar = g_aout + (size_t)n * DMODEL;

    float vals[4];
    float s = 0.f, ss = 0.f;
#pragma unroll
    for (int q = 0; q < 4; q++) {
        int d = tid + q*256;
        float y = xr[d] + ar[d];
        vals[q] = y; s += y; ss += y*y;
    }
#pragma unroll
    for (int o = 16; o > 0; o >>= 1) {
        s  += __shfl_xor_sync(0xffffffffu, s, o);
        ss += __shfl_xor_sync(0xffffffffu, ss, o);
    }
    if ((tid & 31) == 0) { shs[tid>>5] = s; shss[tid>>5] = ss; }
    __syncthreads();
    if (tid < 8) {
        float t1 = shs[tid], t2 = shss[tid];
#pragma unroll
        for (int o = 4; o > 0; o >>= 1) {
            t1 += __shfl_xor_sync(0xffu, t1, o);
            t2 += __shfl_xor_sync(0xffu, t2, o);
        }
        if (tid == 0) { shs[0] = t1; shss[0] = t2; }
    }
    __syncthreads();
    const float mu = shs[0] * (1.0f/DMODEL);
    const float var = shss[0] * (1.0f/DMODEL) - mu*mu;
    const float inv = rsqrtf(var + 1e-5f);

    float* orow = out + (size_t)n * DMODEL;
#pragma unroll
    for (int q = 0; q < 4; q++) {
        int d = tid + q*256;
        orow[d] = (vals[q] - mu) * inv * gamma[d] + beta[d];
    }
}

// ---------------- launch ---------------------------------------------------------
extern "C" void kernel_launch(void* const* d_in, const int* in_sizes, int n_in,
                              void* d_out, int out_size)
{
    (void)in_sizes; (void)n_in; (void)out_size;
    const float* x       = (const float*)d_in[0];
    const float* pos_emb = (const float*)d_in[1];
    const float* bu      = (const float*)d_in[2];
    const float* bv      = (const float*)d_in[3];
    const float* memory  = (const float*)d_in[4];
    const float* W_qkv   = (const float*)d_in[5];
    const float* W_rel   = (const float*)d_in[6];
    const float* W_o     = (const float*)d_in[7];
    const float* gamma   = (const float*)d_in[8];
    const float* beta    = (const float*)d_in[9];
    float* out = (float*)d_out;

    // double-buffered A+B (stage aliased over buffers)
    const int SM_BIG = 2*(128*272 + 128*272);   // 139264 (modes 0,1,5)
    const int SM_AB  = 2*(128*144 + 128*144);   //  73728 (mode 3)

    cudaFuncSetAttribute(gemm_tc<0>, cudaFuncAttributeMaxDynamicSharedMemorySize, SM_BIG);
    cudaFuncSetAttribute(gemm_tc<1>, cudaFuncAttributeMaxDynamicSharedMemorySize, SM_BIG);
    cudaFuncSetAttribute(gemm_tc<3>, cudaFuncAttributeMaxDynamicSharedMemorySize, SM_AB);
    cudaFuncSetAttribute(gemm_tc<5>, cudaFuncAttributeMaxDynamicSharedMemorySize, SM_BIG);
    cudaFuncSetAttribute(flash_attn, cudaFuncAttributeMaxDynamicSharedMemorySize, FSMEM);

    conv_c<<<8192, 256>>>(memory, x);
    conv_pos<<<2048, 256>>>(pos_emb);
    transpose_bf<<<dim3(96, 32), 256>>>(W_qkv, 0, 3072);
    transpose_bf<<<dim3(32, 32), 256>>>(W_rel, 1, 1024);
    transpose_bf<<<dim3(32, 32), 256>>>(W_o,   2, 1024);

    gemm_tc<0><<<dim3(24, 64),    256, SM_BIG>>>(bu, bv);            // QKV
    gemm_tc<1><<<dim3(8, 16),     256, SM_BIG>>>(nullptr, nullptr);  // REL
    gemm_tc<3><<<dim3(16, 8, 64), 256, SM_AB>>>(nullptr, nullptr);   // BD -> shifted bf16
    flash_attn<<<dim3(8, 64), 256, FSMEM>>>();                       // AC+softmax+PV fused
    gemm_tc<5><<<dim3(8, 32),     256, SM_BIG>>>(nullptr, nullptr);  // OUT
    ln_kernel<<<4096, 256>>>(x, gamma, beta, out);
}

// round 13
// speedup vs baseline: 1.5281x; 1.5281x over previous
#include <cuda_runtime.h>
#include <cuda_bf16.h>
#include <math.h>
#include <stdint.h>

#define SQ 1024
#define DMODEL 1024

// ---------------- scratch (static device globals; allocation-free) -------------
__device__ __nv_bfloat16 c_bf  [(size_t)8192*1024];   // concat(memory,x), row n=t*4+b
__device__ __nv_bfloat16 pos_bf[(size_t)2048*1024];
__device__ __nv_bfloat16 wqkvT [(size_t)3072*1024];   // W_qkv^T
__device__ __nv_bfloat16 wrelT [(size_t)1024*1024];
__device__ __nv_bfloat16 woT   [(size_t)1024*1024];
__device__ __nv_bfloat16 g_qu  [(size_t)64*1024*64];  // [bh][i][dh]
__device__ __nv_bfloat16 g_qv  [(size_t)64*1024*64];
__device__ __nv_bfloat16 g_k   [(size_t)64*2048*64];  // [bh][t][dh]
__device__ __nv_bfloat16 g_vT  [(size_t)64*64*2048];  // [bh][dh][t]
__device__ __nv_bfloat16 g_r   [(size_t)16*2048*64];  // [h][p][dh]
__device__ __nv_bfloat16 g_BDs [(size_t)64*1024*2048];// pre-SHIFTED BD, [bh][i][j] bf16
__device__ __nv_bfloat16 g_avec[(size_t)4096*1024];   // [i*4+b][h*64+dh]
__device__ float         g_aout[(size_t)4096*1024];

// ---------------- helpers -------------------------------------------------------
__device__ __forceinline__ uint32_t smem_u32(const void* p){
    uint32_t a;
    asm("{ .reg .u64 t; cvta.to.shared.u64 t, %1; cvt.u32.u64 %0, t; }" : "=r"(a) : "l"(p));
    return a;
}
__device__ __forceinline__ uint32_t pk2(float a, float b){
    return (uint32_t)__bfloat16_as_ushort(__float2bfloat16(a))
         | ((uint32_t)__bfloat16_as_ushort(__float2bfloat16(b)) << 16);
}
__device__ __forceinline__ float lo_bf(uint32_t u){
    return __bfloat162float(__ushort_as_bfloat16((unsigned short)(u & 0xffffu)));
}
__device__ __forceinline__ float hi_bf(uint32_t u){
    return __bfloat162float(__ushort_as_bfloat16((unsigned short)(u >> 16)));
}
__device__ __forceinline__ void ldm_x4(uint32_t* r, uint32_t addr){
    asm volatile("ldmatrix.sync.aligned.m8n8.x4.shared.b16 {%0,%1,%2,%3}, [%4];"
        : "=r"(r[0]), "=r"(r[1]), "=r"(r[2]), "=r"(r[3]) : "r"(addr));
}
__device__ __forceinline__ void mma16816(float* c, const uint32_t* a, const uint32_t* b){
    asm volatile("mma.sync.aligned.m16n8k16.row.col.f32.bf16.bf16.f32 "
        "{%0,%1,%2,%3}, {%4,%5,%6,%7}, {%8,%9}, {%0,%1,%2,%3};"
        : "+f"(c[0]), "+f"(c[1]), "+f"(c[2]), "+f"(c[3])
        : "r"(a[0]), "r"(a[1]), "r"(a[2]), "r"(a[3]), "r"(b[0]), "r"(b[1]));
}

// ---------------- prep kernels --------------------------------------------------
__global__ void __launch_bounds__(256) conv_c(const float* __restrict__ mem, const float* __restrict__ x){
    size_t n = blockIdx.x;
    const float* src = (n < 4096) ? (mem + n*1024) : (x + (n-4096)*1024);
    __nv_bfloat16* dst = c_bf + n*1024;
#pragma unroll
    for (int q = 0; q < 4; q++){ int d = threadIdx.x + q*256; dst[d] = __float2bfloat16(src[d]); }
}
__global__ void __launch_bounds__(256) conv_pos(const float* __restrict__ pe){
    size_t n = blockIdx.x;
    const float* src = pe + n*1024;
    __nv_bfloat16* dst = pos_bf + n*1024;
#pragma unroll
    for (int q = 0; q < 4; q++){ int d = threadIdx.x + q*256; dst[d] = __float2bfloat16(src[d]); }
}
// transpose fp32 [1024][C] -> bf16 [C][1024]
__global__ void __launch_bounds__(256) transpose_bf(const float* __restrict__ src, int mode, int C){
    __shared__ float tile[32][33];
    __nv_bfloat16* dst = (mode == 0) ? wqkvT : (mode == 1) ? wrelT : woT;
    const int R = 1024;
    int c0 = blockIdx.x*32, r0 = blockIdx.y*32;
    int tx = threadIdx.x & 31, ty = threadIdx.x >> 5;
#pragma unroll
    for (int q = 0; q < 4; q++)
        tile[ty + q*8][tx] = src[(size_t)(r0 + ty + q*8)*C + c0 + tx];
    __syncthreads();
#pragma unroll
    for (int q = 0; q < 4; q++)
        dst[(size_t)(c0 + ty + q*8)*R + r0 + tx] = __float2bfloat16(tile[tx][ty + q*8]);
}

// ---------------- generic mma.sync GEMM, register-prefetch pipelined -------------
// MODE 0: QKV   c_bf(8192x1024) @ wqkvT^T  -> scatter qu/qv/k/vT (bf16)
// MODE 1: REL   pos_bf(2048x1024) @ wrelT^T -> g_r (bf16)
// MODE 3: BD    qv(1024x64) @ r^T(2048x64) per bh -> pre-shifted bf16 g_BDs
// MODE 5: OUT   avec(4096x1024) @ woT^T   -> g_aout (f32)
template<int MODE>
__global__ void __launch_bounds__(256) gemm_tc(const float* __restrict__ bu, const float* __restrict__ bv)
{
    constexpr int KC = (MODE == 3) ? 64 : 128;
    constexpr int NT = 128;
    constexpr int NF = NT / 32;
    constexpr int SA = KC*2 + 16;
    constexpr int ASZ = 128*SA;
    constexpr int BSZ = NT*SA;
    extern __shared__ char smem[];
    char* smB = smem + ASZ;
    float* stage = (float*)(smem + ASZ + BSZ);   // [128][NT+1]
    const uint32_t smA32 = smem_u32(smem);
    const uint32_t smB32 = smA32 + ASZ;

    const int tid = threadIdx.x;
    const int lane = tid & 31, wid = tid >> 5;
    const int wm = wid & 1, wn = wid >> 1;

    int m0, n0, bh = 0, h = 0, nchunks;
    if (MODE == 0)      { m0 = blockIdx.y*128; n0 = blockIdx.x*128;
                          // q-output for memory rows (t<1024) is discarded: skip dead tiles
                          if (n0 < 1024 && m0 + 128 <= 4096) return;
                          nchunks = 8; }
    else if (MODE == 1) { m0 = blockIdx.y*128; n0 = blockIdx.x*128; nchunks = 8; }
    else if (MODE == 3) { bh = blockIdx.z; h = bh & 15; m0 = blockIdx.y*128; n0 = blockIdx.x*128;
                          if (n0 + m0 <= 768) return; nchunks = 1; }
    else                { m0 = blockIdx.y*128; n0 = blockIdx.x*128; nchunks = 8; }

    constexpr int RQ = KC/8;
    constexpr int APT = 128*RQ/256;
    constexpr int BPT = NT*RQ/256;
    uint4 pa[APT], pb[BPT];

    auto ldg_chunk = [&](int ch){
        const int k0 = ch * KC;
#pragma unroll
        for (int qq = 0; qq < APT; qq++) {
            int idx = qq*256 + tid;
            int row = idx / RQ, q = idx % RQ;
            const __nv_bfloat16* ap;
            if      (MODE == 0) ap = c_bf   + (size_t)(m0+row)*1024 + k0;
            else if (MODE == 1) ap = pos_bf + (size_t)(m0+row)*1024 + k0;
            else if (MODE == 3) ap = g_qv + ((size_t)bh*1024 + m0+row)*64 + k0;
            else                ap = g_avec + (size_t)(m0+row)*1024 + k0;
            pa[qq] = *(const uint4*)(ap + q*8);
        }
#pragma unroll
        for (int qq = 0; qq < BPT; qq++) {
            int idx = qq*256 + tid;
            int row = idx / RQ, q = idx % RQ;
            const __nv_bfloat16* bp;
            if      (MODE == 0) bp = wqkvT + (size_t)(n0+row)*1024 + k0;
            else if (MODE == 1) bp = wrelT + (size_t)(n0+row)*1024 + k0;
            else if (MODE == 3) bp = g_r + ((size_t)h*2048 + n0+row)*64 + k0;
            else                bp = woT + (size_t)(n0+row)*1024 + k0;
            pb[qq] = *(const uint4*)(bp + q*8);
        }
    };

    float acc[4][NF][4] = {};

    ldg_chunk(0);
    for (int ch = 0; ch < nchunks; ch++) {
        // ---- STS phase: dump prefetched registers to smem ----
#pragma unroll
        for (int qq = 0; qq < APT; qq++) {
            int idx = qq*256 + tid;
            int row = idx / RQ, q = idx % RQ;
            *(uint4*)(smem + row*SA + q*16) = pa[qq];
        }
#pragma unroll
        for (int qq = 0; qq < BPT; qq++) {
            int idx = qq*256 + tid;
            int row = idx / RQ, q = idx % RQ;
            *(uint4*)(smB + row*SA + q*16) = pb[qq];
        }
        __syncthreads();
        // ---- issue next chunk's LDGs; latency overlaps the MMA phase below ----
        if (ch + 1 < nchunks) ldg_chunk(ch + 1);
        // ---- MMA phase ----
#pragma unroll
        for (int ks = 0; ks < KC/16; ks++) {
            const int colb = ks*32 + (lane >> 4)*16;
            uint32_t af[4][4];
#pragma unroll
            for (int mf = 0; mf < 4; mf++) {
                int r = wm*64 + mf*16 + (lane & 15);
                ldm_x4(af[mf], smA32 + r*SA + colb);
            }
            uint32_t bfr[NF][2];
#pragma unroll
            for (int nf2 = 0; nf2 < NF/2; nf2++) {
                uint32_t t4[4];
                int r = wn*(NT/4) + nf2*16 + (lane & 15);
                ldm_x4(t4, smB32 + r*SA + colb);
                bfr[2*nf2][0]   = t4[0]; bfr[2*nf2][1]   = t4[2];
                bfr[2*nf2+1][0] = t4[1]; bfr[2*nf2+1][1] = t4[3];
            }
#pragma unroll
            for (int mf = 0; mf < 4; mf++)
#pragma unroll
                for (int nf = 0; nf < NF; nf++)
                    mma16816(acc[mf][nf], af[mf], bfr[nf]);
        }
        __syncthreads();
    }

    // ---- dump fragments to staged SMEM [128][NT+1] ----
#pragma unroll
    for (int mf = 0; mf < 4; mf++)
#pragma unroll
        for (int nf = 0; nf < NF; nf++) {
            int r0 = wm*64 + mf*16 + (lane >> 2);
            int c0 = wn*(NT/4) + nf*8 + (lane & 3)*2;
            stage[r0*(NT+1)+c0]       = acc[mf][nf][0];
            stage[r0*(NT+1)+c0+1]     = acc[mf][nf][1];
            stage[(r0+8)*(NT+1)+c0]   = acc[mf][nf][2];
            stage[(r0+8)*(NT+1)+c0+1] = acc[mf][nf][3];
        }
    __syncthreads();
    if (tid >= 128) return;

#define STG(r,c) stage[(r)*(NT+1)+(c)]

    if (MODE == 0) {
#pragma unroll
        for (int g = 0; g < 4; g++) {
            const int gc0 = n0 + g*32;
            const int which = gc0 >> 10;
            const int hc0 = gc0 & 1023;
            const int hh = hc0 >> 6, dh0 = hc0 & 63;
            const int n = m0 + tid, t = n >> 2, bb = n & 3;
            if (which == 0) {
                if (t >= 1024) {
                    uint32_t pu[16], pv[16];
#pragma unroll
                    for (int c = 0; c < 32; c += 2) {
                        float v0 = STG(tid, g*32+c), v1 = STG(tid, g*32+c+1);
                        pu[c>>1] = pk2(v0 + bu[hc0+c], v1 + bu[hc0+c+1]);
                        pv[c>>1] = pk2(v0 + bv[hc0+c], v1 + bv[hc0+c+1]);
                    }
                    size_t base = ((size_t)(bb*16+hh)*1024 + (t-1024))*64 + dh0;
#pragma unroll
                    for (int q = 0; q < 4; q++) {
                        *(uint4*)(g_qu + base + q*8) = make_uint4(pu[q*4], pu[q*4+1], pu[q*4+2], pu[q*4+3]);
                        *(uint4*)(g_qv + base + q*8) = make_uint4(pv[q*4], pv[q*4+1], pv[q*4+2], pv[q*4+3]);
                    }
                }
            } else if (which == 1) {
                uint32_t pk[16];
#pragma unroll
                for (int c = 0; c < 32; c += 2) pk[c>>1] = pk2(STG(tid, g*32+c), STG(tid, g*32+c+1));
                size_t base = ((size_t)(bb*16+hh)*2048 + t)*64 + dh0;
#pragma unroll
                for (int q = 0; q < 4; q++)
                    *(uint4*)(g_k + base + q*8) = make_uint4(pk[q*4], pk[q*4+1], pk[q*4+2], pk[q*4+3]);
            } else {
                const int c2 = tid & 31, sub = tid >> 5;
                const int t0 = m0 >> 2;
                uint32_t w[16];
#pragma unroll
                for (int tl = 0; tl < 32; tl += 2)
                    w[tl>>1] = pk2(STG(tl*4+sub, g*32+c2), STG((tl+1)*4+sub, g*32+c2));
                size_t base = ((size_t)(sub*16+hh)*64 + dh0 + c2)*2048 + t0;
#pragma unroll
                for (int q = 0; q < 4; q++)
                    *(uint4*)(g_vT + base + q*8) = make_uint4(w[q*4], w[q*4+1], w[q*4+2], w[q*4+3]);
            }
        }
    } else if (MODE == 1) {
#pragma unroll
        for (int g = 0; g < 4; g++) {
            const int gc0 = n0 + g*32;
            const int hh = gc0 >> 6, dh0 = gc0 & 63;
            uint32_t pk[16];
#pragma unroll
            for (int c = 0; c < 32; c += 2) pk[c>>1] = pk2(STG(tid, g*32+c), STG(tid, g*32+c+1));
            size_t base = ((size_t)hh*2048 + (m0+tid))*64 + dh0;
#pragma unroll
            for (int q = 0; q < 4; q++)
                *(uint4*)(g_r + base + q*8) = make_uint4(pk[q*4], pk[q*4+1], pk[q*4+2], pk[q*4+3]);
        }
    } else if (MODE == 3) {
        // pre-shifted BD store: g_BDs[bh][i][j] = BD[i][p], j = p + i - 1023
        const int i = m0 + tid;
        __nv_bfloat16* dst = g_BDs + ((size_t)bh*1024 + i)*2048;
#pragma unroll
        for (int g = 0; g < 4; g++) {
            const int gc0 = n0 + g*32;
            const int jbase = gc0 + i - 1023;
            float v[32];
#pragma unroll
            for (int c = 0; c < 32; c++) v[c] = STG(tid, g*32+c);
            if (!(jbase & 1)) {
#pragma unroll
                for (int c = 0; c < 32; c += 2) {
                    int j = jbase + c;
                    if (j >= 0) *(uint32_t*)(dst + j) = pk2(v[c], v[c+1]);
                }
            } else {
                if (jbase >= 0) dst[jbase] = __float2bfloat16(v[0]);
#pragma unroll
                for (int c = 1; c < 31; c += 2) {
                    int j = jbase + c;
                    if (j >= 0) *(uint32_t*)(dst + j) = pk2(v[c], v[c+1]);
                }
                if (jbase + 31 >= 0) dst[jbase + 31] = __float2bfloat16(v[31]);
            }
        }
    } else {
        float* dst = g_aout + (size_t)(m0+tid)*1024;
#pragma unroll
        for (int g = 0; g < 4; g++) {
            const int gc0 = n0 + g*32;
#pragma unroll
            for (int c = 0; c < 32; c += 4)
                *(float4*)(dst + gc0 + c) = make_float4(STG(tid, g*32+c),   STG(tid, g*32+c+1),
                                                        STG(tid, g*32+c+2), STG(tid, g*32+c+3));
        }
    }
#undef STG
}

// ---------------- fused flash attention (round-10 exact) -------------------------
// grid (8 i-tiles, 64 bh), 256 threads. Warp w owns query rows [16w, 16w+16).
__global__ void __launch_bounds__(256, 1) flash_attn()
{
    __shared__ __align__(16) char smK[128*144];   // K tile [128 j][64 k], also qu tile at start
    __shared__ __align__(16) char smV[64*272];    // VT tile [64 dh][128 j]
    const uint32_t smK32 = smem_u32(smK);
    const uint32_t smV32 = smem_u32(smV);

    const int bh = blockIdx.y, b = bh >> 4, h = bh & 15;
    const int m0 = (7 - blockIdx.x) * 128;        // longest-work-first
    const int tid = threadIdx.x, lane = tid & 31, w = tid >> 5;
    const int r0 = w * 16;

    // ---- qu tile -> smem -> A fragments (held in regs for all j-tiles) ----
    {
        const __nv_bfloat16* qp = g_qu + ((size_t)bh*1024 + m0)*64;
#pragma unroll
        for (int q4 = 0; q4 < 4; q4++) {
            int idx = q4*256 + tid; int row = idx >> 3, q = idx & 7;
            *(uint4*)(smK + row*144 + q*16) = *(const uint4*)(qp + (size_t)row*64 + q*8);
        }
    }
    __syncthreads();
    uint32_t af[4][4];
#pragma unroll
    for (int ks = 0; ks < 4; ks++)
        ldm_x4(af[ks], smK32 + (r0 + (lane & 15))*144 + ks*32 + (lane >> 4)*16);
    __syncthreads();

    float mrow0 = -1e30f, mrow1 = -1e30f, lrow0 = 0.f, lrow1 = 0.f;
    float oacc[8][4] = {};
    const int ia = m0 + r0 + (lane >> 2);         // row A; row B = ia + 8
    const uint32_t* bdr0 = (const uint32_t*)(g_BDs + ((size_t)bh*1024 + ia)*2048);
    const uint32_t* bdr1 = (const uint32_t*)(g_BDs + ((size_t)bh*1024 + ia + 8)*2048);

    const int ntiles = m0/128 + 9;
    for (int jt = 0; jt < ntiles; jt++) {
        const int j0 = jt * 128;
        {
            const __nv_bfloat16* kp = g_k + ((size_t)bh*2048 + j0)*64;
#pragma unroll
            for (int q4 = 0; q4 < 4; q4++) {
                int idx = q4*256 + tid; int row = idx >> 3, q = idx & 7;
                *(uint4*)(smK + row*144 + q*16) = *(const uint4*)(kp + (size_t)row*64 + q*8);
            }
            const __nv_bfloat16* vp = g_vT + ((size_t)bh*64)*2048 + j0;
#pragma unroll
            for (int q4 = 0; q4 < 4; q4++) {
                int idx = q4*256 + tid; int row = idx >> 4, q = idx & 15;
                *(uint4*)(smV + row*272 + q*16) = *(const uint4*)(vp + (size_t)row*2048 + q*8);
            }
        }
        __syncthreads();

        // ---- S = qu * K^T  (16 rows x 128 cols per warp) ----
        float sacc[16][4] = {};
#pragma unroll
        for (int ks = 0; ks < 4; ks++) {
            uint32_t bfrg[16][2];
#pragma unroll
            for (int nb = 0; nb < 8; nb++) {
                uint32_t t4[4];
                ldm_x4(t4, smK32 + (nb*16 + (lane & 15))*144 + ks*32 + (lane >> 4)*16);
                bfrg[2*nb][0]   = t4[0]; bfrg[2*nb][1]   = t4[2];
                bfrg[2*nb+1][0] = t4[1]; bfrg[2*nb+1][1] = t4[3];
            }
#pragma unroll
            for (int nf = 0; nf < 16; nf++) mma16816(sacc[nf], af[ks], bfrg[nf]);
        }

        // ---- logits: + shifted BD, * scale, causal mask (predicated select) ----
        float tmax0 = -1e30f, tmax1 = -1e30f;
#pragma unroll
        for (int nf = 0; nf < 16; nf++) {
            int j = j0 + nf*8 + (lane & 3)*2;
            uint32_t bdA = bdr0[j >> 1];
            uint32_t bdB = bdr1[j >> 1];
            float a0 = (sacc[nf][0] + lo_bf(bdA)) * 0.125f;
            float a1 = (sacc[nf][1] + hi_bf(bdA)) * 0.125f;
            float b0 = (sacc[nf][2] + lo_bf(bdB)) * 0.125f;
            float b1 = (sacc[nf][3] + hi_bf(bdB)) * 0.125f;
            sacc[nf][0] = (j     <= ia + 1024)     ? a0 : -1e30f;
            sacc[nf][1] = (j + 1 <= ia + 1024)     ? a1 : -1e30f;
            sacc[nf][2] = (j     <= ia + 8 + 1024) ? b0 : -1e30f;
            sacc[nf][3] = (j + 1 <= ia + 8 + 1024) ? b1 : -1e30f;
            tmax0 = fmaxf(tmax0, fmaxf(sacc[nf][0], sacc[nf][1]));
            tmax1 = fmaxf(tmax1, fmaxf(sacc[nf][2], sacc[nf][3]));
        }
        tmax0 = fmaxf(tmax0, __shfl_xor_sync(0xffffffffu, tmax0, 1));
        tmax0 = fmaxf(tmax0, __shfl_xor_sync(0xffffffffu, tmax0, 2));
        tmax1 = fmaxf(tmax1, __shfl_xor_sync(0xffffffffu, tmax1, 1));
        tmax1 = fmaxf(tmax1, __shfl_xor_sync(0xffffffffu, tmax1, 2));

        const float mnew0 = fmaxf(mrow0, tmax0), mnew1 = fmaxf(mrow1, tmax1);
        const float f0 = __expf(mrow0 - mnew0), f1 = __expf(mrow1 - mnew1);
        mrow0 = mnew0; mrow1 = mnew1;
        lrow0 *= f0; lrow1 *= f1;
#pragma unroll
        for (int nf = 0; nf < 8; nf++) {
            oacc[nf][0] *= f0; oacc[nf][1] *= f0;
            oacc[nf][2] *= f1; oacc[nf][3] *= f1;
        }

        // ---- P = exp(S - m), pack acc frags -> A frags ----
        uint32_t pf[8][4];
        float s0 = 0.f, s1 = 0.f;
#pragma unroll
        for (int kf = 0; kf < 8; kf++) {
            float e00 = __expf(sacc[2*kf][0]   - mnew0), e01 = __expf(sacc[2*kf][1]   - mnew0);
            float e02 = __expf(sacc[2*kf][2]   - mnew1), e03 = __expf(sacc[2*kf][3]   - mnew1);
            float e10 = __expf(sacc[2*kf+1][0] - mnew0), e11 = __expf(sacc[2*kf+1][1] - mnew0);
            float e12 = __expf(sacc[2*kf+1][2] - mnew1), e13 = __expf(sacc[2*kf+1][3] - mnew1);
            s0 += e00 + e01 + e10 + e11;
            s1 += e02 + e03 + e12 + e13;
            pf[kf][0] = pk2(e00, e01);
            pf[kf][1] = pk2(e02, e03);
            pf[kf][2] = pk2(e10, e11);
            pf[kf][3] = pk2(e12, e13);
        }
        lrow0 += s0; lrow1 += s1;

        // ---- O += P * V ----
#pragma unroll
        for (int kf = 0; kf < 8; kf++) {
            uint32_t bv[8][2];
#pragma unroll
            for (int nb = 0; nb < 4; nb++) {
                uint32_t t4[4];
                ldm_x4(t4, smV32 + (nb*16 + (lane & 15))*272 + kf*32 + (lane >> 4)*16);
                bv[2*nb][0]   = t4[0]; bv[2*nb][1]   = t4[2];
                bv[2*nb+1][0] = t4[1]; bv[2*nb+1][1] = t4[3];
            }
#pragma unroll
            for (int nf = 0; nf < 8; nf++) mma16816(oacc[nf], pf[kf], bv[nf]);
        }
        __syncthreads();
    }

    // ---- finalize: O /= l, write bf16 to g_avec ----
    lrow0 += __shfl_xor_sync(0xffffffffu, lrow0, 1);
    lrow0 += __shfl_xor_sync(0xffffffffu, lrow0, 2);
    lrow1 += __shfl_xor_sync(0xffffffffu, lrow1, 1);
    lrow1 += __shfl_xor_sync(0xffffffffu, lrow1, 2);
    const float inv0 = 1.f / lrow0, inv1 = 1.f / lrow1;

    __nv_bfloat16* d0 = g_avec + ((size_t)ia*4 + b)*1024 + h*64;
    __nv_bfloat16* d1 = g_avec + ((size_t)(ia+8)*4 + b)*1024 + h*64;
#pragma unroll
    for (int nf = 0; nf < 8; nf++) {
        int c = nf*8 + (lane & 3)*2;
        *(uint32_t*)(d0 + c) = pk2(oacc[nf][0]*inv0, oacc[nf][1]*inv0);
        *(uint32_t*)(d1 + c) = pk2(oacc[nf][2]*inv1, oacc[nf][3]*inv1);
    }
}

// ---------------- residual + LayerNorm ------------------------------------------
__global__ void __launch_bounds__(256) ln_kernel(
    const float* __restrict__ x, const float* __restrict__ gamma,
    const float* __restrict__ beta, float* __restrict__ out)
{
    __shared__ float shs[8], shss[8];
    const int n = blockIdx.x;
    const int tid = threadIdx.x;
    const float* xr = x + (size_t)n * DMODEL;
    const float* ar = g_aout + (size_t)n * DMODEL;

    float vals[4];
    float s = 0.f, ss = 0.f;
#pragma unroll
    for (int q = 0; q < 4; q++) {
        int d = tid + q*256;
        float y = xr[d] + ar[d];
        vals[q] = y; s += y; ss += y*y;
    }
#pragma unroll
    for (int o = 16; o > 0; o >>= 1) {
        s  += __shfl_xor_sync(0xffffffffu, s, o);
        ss += __shfl_xor_sync(0xffffffffu, ss, o);
    }
    if ((tid & 31) == 0) { shs[tid>>5] = s; shss[tid>>5] = ss; }
    __syncthreads();
    if (tid < 8) {
        float t1 = shs[tid], t2 = shss[tid];
#pragma unroll
        for (int o = 4; o > 0; o >>= 1) {
            t1 += __shfl_xor_sync(0xffu, t1, o);
            t2 += __shfl_xor_sync(0xffu, t2, o);
        }
        if (tid == 0) { shs[0] = t1; shss[0] = t2; }
    }
    __syncthreads();
    const float mu = shs[0] * (1.0f/DMODEL);
    const float var = shss[0] * (1.0f/DMODEL) - mu*mu;
    const float inv = rsqrtf(var + 1e-5f);

    float* orow = out + (size_t)n * DMODEL;
#pragma unroll
    for (int q = 0; q < 4; q++) {
        int d = tid + q*256;
        orow[d] = (vals[q] - mu) * inv * gamma[d] + beta[d];
    }
}

// ---------------- launch ---------------------------------------------------------
extern "C" void kernel_launch(void* const* d_in, const int* in_sizes, int n_in,
                              void* d_out, int out_size)
{
    (void)in_sizes; (void)n_in; (void)out_size;
    const float* x       = (const float*)d_in[0];
    const float* pos_emb = (const float*)d_in[1];
    const float* bu      = (const float*)d_in[2];
    const float* bv      = (const float*)d_in[3];
    const float* memory  = (const float*)d_in[4];
    const float* W_qkv   = (const float*)d_in[5];
    const float* W_rel   = (const float*)d_in[6];
    const float* W_o     = (const float*)d_in[7];
    const float* gamma   = (const float*)d_in[8];
    const float* beta    = (const float*)d_in[9];
    float* out = (float*)d_out;

    const int SM_BIG = 128*272 + 128*272 + 128*129*4;  // 135680 (modes 0,1,5)
    const int SM_AB  = 128*144 + 128*144 + 128*129*4;  // 102912 (mode 3)

    cudaFuncSetAttribute(gemm_tc<0>, cudaFuncAttributeMaxDynamicSharedMemorySize, SM_BIG);
    cudaFuncSetAttribute(gemm_tc<1>, cudaFuncAttributeMaxDynamicSharedMemorySize, SM_BIG);
    cudaFuncSetAttribute(gemm_tc<3>, cudaFuncAttributeMaxDynamicSharedMemorySize, SM_AB);
    cudaFuncSetAttribute(gemm_tc<5>, cudaFuncAttributeMaxDynamicSharedMemorySize, SM_BIG);

    conv_c<<<8192, 256>>>(memory, x);
    conv_pos<<<2048, 256>>>(pos_emb);
    transpose_bf<<<dim3(96, 32), 256>>>(W_qkv, 0, 3072);
    transpose_bf<<<dim3(32, 32), 256>>>(W_rel, 1, 1024);
    transpose_bf<<<dim3(32, 32), 256>>>(W_o,   2, 1024);

    gemm_tc<0><<<dim3(24, 64),    256, SM_BIG>>>(bu, bv);            // QKV (dead tiles skipped)
    gemm_tc<1><<<dim3(8, 16),     256, SM_BIG>>>(nullptr, nullptr);  // REL
    gemm_tc<3><<<dim3(16, 8, 64), 256, SM_AB>>>(nullptr, nullptr);   // BD -> shifted bf16
    flash_attn<<<dim3(8, 64), 256>>>();                              // AC+softmax+PV fused
    gemm_tc<5><<<dim3(8, 32),     256, SM_BIG>>>(nullptr, nullptr);  // OUT
    ln_kernel<<<4096, 256>>>(x, gamma, beta, out);
}

// round 14
// speedup vs baseline: 1.5882x; 1.0393x over previous
#include <cuda_runtime.h>
#include <cuda_bf16.h>
#include <math.h>
#include <stdint.h>

#define SQ 1024
#define DMODEL 1024
// logits computed in log2 domain: fold 0.125*log2(e) into qu/qv at QKV epilogue
#define SCL2 0.18033688f

// ---------------- scratch (static device globals; allocation-free) -------------
__device__ __nv_bfloat16 c_bf  [(size_t)8192*1024];   // concat(memory,x), row n=t*4+b
__device__ __nv_bfloat16 pos_bf[(size_t)2048*1024];
__device__ __nv_bfloat16 wqkvT [(size_t)3072*1024];   // W_qkv^T
__device__ __nv_bfloat16 wrelT [(size_t)1024*1024];
__device__ __nv_bfloat16 woT   [(size_t)1024*1024];
__device__ __nv_bfloat16 g_qu  [(size_t)64*1024*64];  // [bh][i][dh]  (pre-scaled)
__device__ __nv_bfloat16 g_qv  [(size_t)64*1024*64];  //              (pre-scaled)
__device__ __nv_bfloat16 g_k   [(size_t)64*2048*64];  // [bh][t][dh]
__device__ __nv_bfloat16 g_vT  [(size_t)64*64*2048];  // [bh][dh][t]
__device__ __nv_bfloat16 g_r   [(size_t)16*2048*64];  // [h][p][dh]
__device__ __nv_bfloat16 g_BDs [(size_t)64*1024*2048];// pre-SHIFTED scaled BD, [bh][i][j] bf16
__device__ __nv_bfloat16 g_avec[(size_t)4096*1024];   // [i*4+b][h*64+dh]
__device__ float         g_aout[(size_t)4096*1024];

// ---------------- helpers -------------------------------------------------------
__device__ __forceinline__ uint32_t smem_u32(const void* p){
    uint32_t a;
    asm("{ .reg .u64 t; cvta.to.shared.u64 t, %1; cvt.u32.u64 %0, t; }" : "=r"(a) : "l"(p));
    return a;
}
__device__ __forceinline__ uint32_t pk2(float a, float b){
    return (uint32_t)__bfloat16_as_ushort(__float2bfloat16(a))
         | ((uint32_t)__bfloat16_as_ushort(__float2bfloat16(b)) << 16);
}
__device__ __forceinline__ float lo_bf(uint32_t u){
    return __bfloat162float(__ushort_as_bfloat16((unsigned short)(u & 0xffffu)));
}
__device__ __forceinline__ float hi_bf(uint32_t u){
    return __bfloat162float(__ushort_as_bfloat16((unsigned short)(u >> 16)));
}
__device__ __forceinline__ float ex2(float x){
    float y; asm("ex2.approx.f32 %0, %1;" : "=f"(y) : "f"(x)); return y;
}
__device__ __forceinline__ void ldm_x4(uint32_t* r, uint32_t addr){
    asm volatile("ldmatrix.sync.aligned.m8n8.x4.shared.b16 {%0,%1,%2,%3}, [%4];"
        : "=r"(r[0]), "=r"(r[1]), "=r"(r[2]), "=r"(r[3]) : "r"(addr));
}
__device__ __forceinline__ void mma16816(float* c, const uint32_t* a, const uint32_t* b){
    asm volatile("mma.sync.aligned.m16n8k16.row.col.f32.bf16.bf16.f32 "
        "{%0,%1,%2,%3}, {%4,%5,%6,%7}, {%8,%9}, {%0,%1,%2,%3};"
        : "+f"(c[0]), "+f"(c[1]), "+f"(c[2]), "+f"(c[3])
        : "r"(a[0]), "r"(a[1]), "r"(a[2]), "r"(a[3]), "r"(b[0]), "r"(b[1]));
}

// ---------------- prep kernels --------------------------------------------------
__global__ void __launch_bounds__(256) conv_in(const float* __restrict__ mem,
                                               const float* __restrict__ x,
                                               const float* __restrict__ pe){
    size_t n = blockIdx.x;
    const float* src; __nv_bfloat16* dst;
    if (n < 8192) {
        src = (n < 4096) ? (mem + n*1024) : (x + (n-4096)*1024);
        dst = c_bf + n*1024;
    } else {
        size_t m = n - 8192;
        src = pe + m*1024;
        dst = pos_bf + m*1024;
    }
#pragma unroll
    for (int q = 0; q < 4; q++){ int d = threadIdx.x + q*256; dst[d] = __float2bfloat16(src[d]); }
}
// transpose fp32 [1024][C] -> bf16 [C][1024]
__global__ void __launch_bounds__(256) transpose_bf(const float* __restrict__ src, int mode, int C){
    __shared__ float tile[32][33];
    __nv_bfloat16* dst = (mode == 0) ? wqkvT : (mode == 1) ? wrelT : woT;
    const int R = 1024;
    int c0 = blockIdx.x*32, r0 = blockIdx.y*32;
    int tx = threadIdx.x & 31, ty = threadIdx.x >> 5;
#pragma unroll
    for (int q = 0; q < 4; q++)
        tile[ty + q*8][tx] = src[(size_t)(r0 + ty + q*8)*C + c0 + tx];
    __syncthreads();
#pragma unroll
    for (int q = 0; q < 4; q++)
        dst[(size_t)(c0 + ty + q*8)*R + r0 + tx] = __float2bfloat16(tile[tx][ty + q*8]);
}

// ---------------- generic mma.sync GEMM, register-prefetch pipelined -------------
// MODE 0: QKV   c_bf(8192x1024) @ wqkvT^T  -> scatter qu/qv/k/vT (bf16)
// MODE 1: REL   pos_bf(2048x1024) @ wrelT^T -> g_r (bf16)
// MODE 3: BD    qv(1024x64) @ r^T(2048x64) per bh -> pre-shifted bf16 g_BDs
// MODE 5: OUT   avec(4096x1024) @ woT^T   -> g_aout (f32)
template<int MODE>
__global__ void __launch_bounds__(256) gemm_tc(const float* __restrict__ bu, const float* __restrict__ bv)
{
    constexpr int KC = (MODE == 3) ? 64 : 128;
    constexpr int NT = 128;
    constexpr int NF = NT / 32;
    constexpr int SA = KC*2 + 16;
    constexpr int ASZ = 128*SA;
    constexpr int BSZ = NT*SA;
    extern __shared__ char smem[];
    char* smB = smem + ASZ;
    float* stage = (float*)(smem + ASZ + BSZ);   // [128][NT+1]
    const uint32_t smA32 = smem_u32(smem);
    const uint32_t smB32 = smA32 + ASZ;

    const int tid = threadIdx.x;
    const int lane = tid & 31, wid = tid >> 5;
    const int wm = wid & 1, wn = wid >> 1;

    int m0, n0, bh = 0, h = 0, nchunks;
    if (MODE == 0)      { m0 = blockIdx.y*128; n0 = blockIdx.x*128;
                          if (n0 < 1024 && m0 + 128 <= 4096) return;   // dead q tiles
                          nchunks = 8; }
    else if (MODE == 1) { m0 = blockIdx.y*128; n0 = blockIdx.x*128; nchunks = 8; }
    else if (MODE == 3) { bh = blockIdx.z; h = bh & 15; m0 = blockIdx.y*128; n0 = blockIdx.x*128;
                          if (n0 + m0 <= 768) return; nchunks = 1; }
    else                { m0 = blockIdx.y*128; n0 = blockIdx.x*128; nchunks = 8; }

    constexpr int RQ = KC/8;
    constexpr int APT = 128*RQ/256;
    constexpr int BPT = NT*RQ/256;
    uint4 pa[APT], pb[BPT];

    auto ldg_chunk = [&](int ch){
        const int k0 = ch * KC;
#pragma unroll
        for (int qq = 0; qq < APT; qq++) {
            int idx = qq*256 + tid;
            int row = idx / RQ, q = idx % RQ;
            const __nv_bfloat16* ap;
            if      (MODE == 0) ap = c_bf   + (size_t)(m0+row)*1024 + k0;
            else if (MODE == 1) ap = pos_bf + (size_t)(m0+row)*1024 + k0;
            else if (MODE == 3) ap = g_qv + ((size_t)bh*1024 + m0+row)*64 + k0;
            else                ap = g_avec + (size_t)(m0+row)*1024 + k0;
            pa[qq] = *(const uint4*)(ap + q*8);
        }
#pragma unroll
        for (int qq = 0; qq < BPT; qq++) {
            int idx = qq*256 + tid;
            int row = idx / RQ, q = idx % RQ;
            const __nv_bfloat16* bp;
            if      (MODE == 0) bp = wqkvT + (size_t)(n0+row)*1024 + k0;
            else if (MODE == 1) bp = wrelT + (size_t)(n0+row)*1024 + k0;
            else if (MODE == 3) bp = g_r + ((size_t)h*2048 + n0+row)*64 + k0;
            else                bp = woT + (size_t)(n0+row)*1024 + k0;
            pb[qq] = *(const uint4*)(bp + q*8);
        }
    };

    float acc[4][NF][4] = {};

    ldg_chunk(0);
    for (int ch = 0; ch < nchunks; ch++) {
        // ---- STS phase: dump prefetched registers to smem ----
#pragma unroll
        for (int qq = 0; qq < APT; qq++) {
            int idx = qq*256 + tid;
            int row = idx / RQ, q = idx % RQ;
            *(uint4*)(smem + row*SA + q*16) = pa[qq];
        }
#pragma unroll
        for (int qq = 0; qq < BPT; qq++) {
            int idx = qq*256 + tid;
            int row = idx / RQ, q = idx % RQ;
            *(uint4*)(smB + row*SA + q*16) = pb[qq];
        }
        __syncthreads();
        if (ch + 1 < nchunks) ldg_chunk(ch + 1);
        // ---- MMA phase ----
#pragma unroll
        for (int ks = 0; ks < KC/16; ks++) {
            const int colb = ks*32 + (lane >> 4)*16;
            uint32_t af[4][4];
#pragma unroll
            for (int mf = 0; mf < 4; mf++) {
                int r = wm*64 + mf*16 + (lane & 15);
                ldm_x4(af[mf], smA32 + r*SA + colb);
            }
            uint32_t bfr[NF][2];
#pragma unroll
            for (int nf2 = 0; nf2 < NF/2; nf2++) {
                uint32_t t4[4];
                int r = wn*(NT/4) + nf2*16 + (lane & 15);
                ldm_x4(t4, smB32 + r*SA + colb);
                bfr[2*nf2][0]   = t4[0]; bfr[2*nf2][1]   = t4[2];
                bfr[2*nf2+1][0] = t4[1]; bfr[2*nf2+1][1] = t4[3];
            }
#pragma unroll
            for (int mf = 0; mf < 4; mf++)
#pragma unroll
                for (int nf = 0; nf < NF; nf++)
                    mma16816(acc[mf][nf], af[mf], bfr[nf]);
        }
        __syncthreads();
    }

    // ---- dump fragments to staged SMEM [128][NT+1] ----
#pragma unroll
    for (int mf = 0; mf < 4; mf++)
#pragma unroll
        for (int nf = 0; nf < NF; nf++) {
            int r0 = wm*64 + mf*16 + (lane >> 2);
            int c0 = wn*(NT/4) + nf*8 + (lane & 3)*2;
            stage[r0*(NT+1)+c0]       = acc[mf][nf][0];
            stage[r0*(NT+1)+c0+1]     = acc[mf][nf][1];
            stage[(r0+8)*(NT+1)+c0]   = acc[mf][nf][2];
            stage[(r0+8)*(NT+1)+c0+1] = acc[mf][nf][3];
        }
    __syncthreads();
    if (tid >= 128) return;

#define STG(r,c) stage[(r)*(NT+1)+(c)]

    if (MODE == 0) {
#pragma unroll
        for (int g = 0; g < 4; g++) {
            const int gc0 = n0 + g*32;
            const int which = gc0 >> 10;
            const int hc0 = gc0 & 1023;
            const int hh = hc0 >> 6, dh0 = hc0 & 63;
            const int n = m0 + tid, t = n >> 2, bb = n & 3;
            if (which == 0) {
                if (t >= 1024) {
                    uint32_t pu[16], pv[16];
#pragma unroll
                    for (int c = 0; c < 32; c += 2) {
                        float v0 = STG(tid, g*32+c), v1 = STG(tid, g*32+c+1);
                        pu[c>>1] = pk2((v0 + bu[hc0+c])*SCL2, (v1 + bu[hc0+c+1])*SCL2);
                        pv[c>>1] = pk2((v0 + bv[hc0+c])*SCL2, (v1 + bv[hc0+c+1])*SCL2);
                    }
                    size_t base = ((size_t)(bb*16+hh)*1024 + (t-1024))*64 + dh0;
#pragma unroll
                    for (int q = 0; q < 4; q++) {
                        *(uint4*)(g_qu + base + q*8) = make_uint4(pu[q*4], pu[q*4+1], pu[q*4+2], pu[q*4+3]);
                        *(uint4*)(g_qv + base + q*8) = make_uint4(pv[q*4], pv[q*4+1], pv[q*4+2], pv[q*4+3]);
                    }
                }
            } else if (which == 1) {
                uint32_t pk[16];
#pragma unroll
                for (int c = 0; c < 32; c += 2) pk[c>>1] = pk2(STG(tid, g*32+c), STG(tid, g*32+c+1));
                size_t base = ((size_t)(bb*16+hh)*2048 + t)*64 + dh0;
#pragma unroll
                for (int q = 0; q < 4; q++)
                    *(uint4*)(g_k + base + q*8) = make_uint4(pk[q*4], pk[q*4+1], pk[q*4+2], pk[q*4+3]);
            } else {
                const int c2 = tid & 31, sub = tid >> 5;
                const int t0 = m0 >> 2;
                uint32_t w[16];
#pragma unroll
                for (int tl = 0; tl < 32; tl += 2)
                    w[tl>>1] = pk2(STG(tl*4+sub, g*32+c2), STG((tl+1)*4+sub, g*32+c2));
                size_t base = ((size_t)(sub*16+hh)*64 + dh0 + c2)*2048 + t0;
#pragma unroll
                for (int q = 0; q < 4; q++)
                    *(uint4*)(g_vT + base + q*8) = make_uint4(w[q*4], w[q*4+1], w[q*4+2], w[q*4+3]);
            }
        }
    } else if (MODE == 1) {
#pragma unroll
        for (int g = 0; g < 4; g++) {
            const int gc0 = n0 + g*32;
            const int hh = gc0 >> 6, dh0 = gc0 & 63;
            uint32_t pk[16];
#pragma unroll
            for (int c = 0; c < 32; c += 2) pk[c>>1] = pk2(STG(tid, g*32+c), STG(tid, g*32+c+1));
            size_t base = ((size_t)hh*2048 + (m0+tid))*64 + dh0;
#pragma unroll
            for (int q = 0; q < 4; q++)
                *(uint4*)(g_r + base + q*8) = make_uint4(pk[q*4], pk[q*4+1], pk[q*4+2], pk[q*4+3]);
        }
    } else if (MODE == 3) {
        // pre-shifted BD store: g_BDs[bh][i][j] = BD[i][p], j = p + i - 1023
        const int i = m0 + tid;
        __nv_bfloat16* dst = g_BDs + ((size_t)bh*1024 + i)*2048;
#pragma unroll
        for (int g = 0; g < 4; g++) {
            const int gc0 = n0 + g*32;
            const int jbase = gc0 + i - 1023;
            float v[32];
#pragma unroll
            for (int c = 0; c < 32; c++) v[c] = STG(tid, g*32+c);
            if (!(jbase & 1)) {
#pragma unroll
                for (int c = 0; c < 32; c += 2) {
                    int j = jbase + c;
                    if (j >= 0) *(uint32_t*)(dst + j) = pk2(v[c], v[c+1]);
                }
            } else {
                if (jbase >= 0) dst[jbase] = __float2bfloat16(v[0]);
#pragma unroll
                for (int c = 1; c < 31; c += 2) {
                    int j = jbase + c;
                    if (j >= 0) *(uint32_t*)(dst + j) = pk2(v[c], v[c+1]);
                }
                if (jbase + 31 >= 0) dst[jbase + 31] = __float2bfloat16(v[31]);
            }
        }
    } else {
        float* dst = g_aout + (size_t)(m0+tid)*1024;
#pragma unroll
        for (int g = 0; g < 4; g++) {
            const int gc0 = n0 + g*32;
#pragma unroll
            for (int c = 0; c < 32; c += 4)
                *(float4*)(dst + gc0 + c) = make_float4(STG(tid, g*32+c),   STG(tid, g*32+c+1),
                                                        STG(tid, g*32+c+2), STG(tid, g*32+c+3));
        }
    }
#undef STG
}

// ---------------- fused flash attention, register-prefetch pipelined -------------
// grid (8 i-tiles, 64 bh), 256 threads. Warp w owns query rows [16w, 16w+16).
// Logits are in log2 domain (scale folded into qu/qv); exp -> ex2.
__global__ void __launch_bounds__(256, 1) flash_attn()
{
    __shared__ __align__(16) char smK[128*144];   // K tile [128 j][64 k], also qu tile at start
    __shared__ __align__(16) char smV[64*272];    // VT tile [64 dh][128 j]
    const uint32_t smK32 = smem_u32(smK);
    const uint32_t smV32 = smem_u32(smV);

    const int bh = blockIdx.y, b = bh >> 4, h = bh & 15;
    const int m0 = (7 - blockIdx.x) * 128;        // longest-work-first
    const int tid = threadIdx.x, lane = tid & 31, w = tid >> 5;
    const int r0 = w * 16;

    // ---- qu tile -> smem -> A fragments (held in regs for all j-tiles) ----
    {
        const __nv_bfloat16* qp = g_qu + ((size_t)bh*1024 + m0)*64;
#pragma unroll
        for (int q4 = 0; q4 < 4; q4++) {
            int idx = q4*256 + tid; int row = idx >> 3, q = idx & 7;
            *(uint4*)(smK + row*144 + q*16) = *(const uint4*)(qp + (size_t)row*64 + q*8);
        }
    }
    __syncthreads();
    uint32_t af[4][4];
#pragma unroll
    for (int ks = 0; ks < 4; ks++)
        ldm_x4(af[ks], smK32 + (r0 + (lane & 15))*144 + ks*32 + (lane >> 4)*16);
    __syncthreads();

    uint4 pkr[4], pvr[4];
    auto ldg_kv = [&](int jt){
        const int j0n = jt * 128;
        const __nv_bfloat16* kp = g_k + ((size_t)bh*2048 + j0n)*64;
#pragma unroll
        for (int q4 = 0; q4 < 4; q4++) {
            int idx = q4*256 + tid; int row = idx >> 3, q = idx & 7;
            pkr[q4] = *(const uint4*)(kp + (size_t)row*64 + q*8);
        }
        const __nv_bfloat16* vp = g_vT + ((size_t)bh*64)*2048 + j0n;
#pragma unroll
        for (int q4 = 0; q4 < 4; q4++) {
            int idx = q4*256 + tid; int row = idx >> 4, q = idx & 15;
            pvr[q4] = *(const uint4*)(vp + (size_t)row*2048 + q*8);
        }
    };

    float mrow0 = -1e30f, mrow1 = -1e30f, lrow0 = 0.f, lrow1 = 0.f;
    float oacc[8][4] = {};
    const int ia = m0 + r0 + (lane >> 2);         // row A; row B = ia + 8
    const uint32_t* bdr0 = (const uint32_t*)(g_BDs + ((size_t)bh*1024 + ia)*2048);
    const uint32_t* bdr1 = (const uint32_t*)(g_BDs + ((size_t)bh*1024 + ia + 8)*2048);

    const int ntiles = m0/128 + 9;
    ldg_kv(0);
    for (int jt = 0; jt < ntiles; jt++) {
        const int j0 = jt * 128;
        // ---- STS phase: dump prefetched K/V regs to smem ----
#pragma unroll
        for (int q4 = 0; q4 < 4; q4++) {
            int idx = q4*256 + tid; int row = idx >> 3, q = idx & 7;
            *(uint4*)(smK + row*144 + q*16) = pkr[q4];
        }
#pragma unroll
        for (int q4 = 0; q4 < 4; q4++) {
            int idx = q4*256 + tid; int row = idx >> 4, q = idx & 15;
            *(uint4*)(smV + row*272 + q*16) = pvr[q4];
        }
        __syncthreads();
        if (jt + 1 < ntiles) ldg_kv(jt + 1);

        // ---- prefetch shifted-BD for this tile (consumed after S-MMAs) ----
        uint32_t bda[16], bdb[16];
        {
            const uint32_t* b0p = bdr0 + (j0 >> 1) + (lane & 3);
            const uint32_t* b1p = bdr1 + (j0 >> 1) + (lane & 3);
#pragma unroll
            for (int nf = 0; nf < 16; nf++) { bda[nf] = b0p[nf*4]; bdb[nf] = b1p[nf*4]; }
        }

        // ---- S = qu * K^T  (16 rows x 128 cols per warp) ----
        float sacc[16][4] = {};
#pragma unroll
        for (int ks = 0; ks < 4; ks++) {
            uint32_t bfrg[16][2];
#pragma unroll
            for (int nb = 0; nb < 8; nb++) {
                uint32_t t4[4];
                ldm_x4(t4, smK32 + (nb*16 + (lane & 15))*144 + ks*32 + (lane >> 4)*16);
                bfrg[2*nb][0]   = t4[0]; bfrg[2*nb][1]   = t4[2];
                bfrg[2*nb+1][0] = t4[1]; bfrg[2*nb+1][1] = t4[3];
            }
#pragma unroll
            for (int nf = 0; nf < 16; nf++) mma16816(sacc[nf], af[ks], bfrg[nf]);
        }

        // ---- logits (log2 domain): + shifted BD, causal mask ----
        float tmax0 = -1e30f, tmax1 = -1e30f;
#pragma unroll
        for (int nf = 0; nf < 16; nf++) {
            int j = j0 + nf*8 + (lane & 3)*2;
            float a0 = sacc[nf][0] + lo_bf(bda[nf]);
            float a1 = sacc[nf][1] + hi_bf(bda[nf]);
            float b0 = sacc[nf][2] + lo_bf(bdb[nf]);
            float b1 = sacc[nf][3] + hi_bf(bdb[nf]);
            sacc[nf][0] = (j     <= ia + 1024)     ? a0 : -1e30f;
            sacc[nf][1] = (j + 1 <= ia + 1024)     ? a1 : -1e30f;
            sacc[nf][2] = (j     <= ia + 8 + 1024) ? b0 : -1e30f;
            sacc[nf][3] = (j + 1 <= ia + 8 + 1024) ? b1 : -1e30f;
            tmax0 = fmaxf(tmax0, fmaxf(sacc[nf][0], sacc[nf][1]));
            tmax1 = fmaxf(tmax1, fmaxf(sacc[nf][2], sacc[nf][3]));
        }
        tmax0 = fmaxf(tmax0, __shfl_xor_sync(0xffffffffu, tmax0, 1));
        tmax0 = fmaxf(tmax0, __shfl_xor_sync(0xffffffffu, tmax0, 2));
        tmax1 = fmaxf(tmax1, __shfl_xor_sync(0xffffffffu, tmax1, 1));
        tmax1 = fmaxf(tmax1, __shfl_xor_sync(0xffffffffu, tmax1, 2));

        const float mnew0 = fmaxf(mrow0, tmax0), mnew1 = fmaxf(mrow1, tmax1);
        const float f0 = ex2(mrow0 - mnew0), f1 = ex2(mrow1 - mnew1);
        mrow0 = mnew0; mrow1 = mnew1;
        lrow0 *= f0; lrow1 *= f1;
#pragma unroll
        for (int nf = 0; nf < 8; nf++) {
            oacc[nf][0] *= f0; oacc[nf][1] *= f0;
            oacc[nf][2] *= f1; oacc[nf][3] *= f1;
        }

        // ---- P = 2^(S - m), pack acc frags -> A frags ----
        uint32_t pf[8][4];
        float s0 = 0.f, s1 = 0.f;
#pragma unroll
        for (int kf = 0; kf < 8; kf++) {
            float e00 = ex2(sacc[2*kf][0]   - mnew0), e01 = ex2(sacc[2*kf][1]   - mnew0);
            float e02 = ex2(sacc[2*kf][2]   - mnew1), e03 = ex2(sacc[2*kf][3]   - mnew1);
            float e10 = ex2(sacc[2*kf+1][0] - mnew0), e11 = ex2(sacc[2*kf+1][1] - mnew0);
            float e12 = ex2(sacc[2*kf+1][2] - mnew1), e13 = ex2(sacc[2*kf+1][3] - mnew1);
            s0 += e00 + e01 + e10 + e11;
            s1 += e02 + e03 + e12 + e13;
            pf[kf][0] = pk2(e00, e01);
            pf[kf][1] = pk2(e02, e03);
            pf[kf][2] = pk2(e10, e11);
            pf[kf][3] = pk2(e12, e13);
        }
        lrow0 += s0; lrow1 += s1;

        // ---- O += P * V ----
#pragma unroll
        for (int kf = 0; kf < 8; kf++) {
            uint32_t bv[8][2];
#pragma unroll
            for (int nb = 0; nb < 4; nb++) {
                uint32_t t4[4];
                ldm_x4(t4, smV32 + (nb*16 + (lane & 15))*272 + kf*32 + (lane >> 4)*16);
                bv[2*nb][0]   = t4[0]; bv[2*nb][1]   = t4[2];
                bv[2*nb+1][0] = t4[1]; bv[2*nb+1][1] = t4[3];
            }
#pragma unroll
            for (int nf = 0; nf < 8; nf++) mma16816(oacc[nf], pf[kf], bv[nf]);
        }
        __syncthreads();
    }

    // ---- finalize: O /= l, write bf16 to g_avec ----
    lrow0 += __shfl_xor_sync(0xffffffffu, lrow0, 1);
    lrow0 += __shfl_xor_sync(0xffffffffu, lrow0, 2);
    lrow1 += __shfl_xor_sync(0xffffffffu, lrow1, 1);
    lrow1 += __shfl_xor_sync(0xffffffffu, lrow1, 2);
    const float inv0 = 1.f / lrow0, inv1 = 1.f / lrow1;

    __nv_bfloat16* d0 = g_avec + ((size_t)ia*4 + b)*1024 + h*64;
    __nv_bfloat16* d1 = g_avec + ((size_t)(ia+8)*4 + b)*1024 + h*64;
#pragma unroll
    for (int nf = 0; nf < 8; nf++) {
        int c = nf*8 + (lane & 3)*2;
        *(uint32_t*)(d0 + c) = pk2(oacc[nf][0]*inv0, oacc[nf][1]*inv0);
        *(uint32_t*)(d1 + c) = pk2(oacc[nf][2]*inv1, oacc[nf][3]*inv1);
    }
}

// ---------------- residual + LayerNorm ------------------------------------------
__global__ void __launch_bounds__(256) ln_kernel(
    const float* __restrict__ x, const float* __restrict__ gamma,
    const float* __restrict__ beta, float* __restrict__ out)
{
    __shared__ float shs[8], shss[8];
    const int n = blockIdx.x;
    const int tid = threadIdx.x;
    const float* xr = x + (size_t)n * DMODEL;
    const float* ar = g_aout + (size_t)n * DMODEL;

    float vals[4];
    float s = 0.f, ss = 0.f;
#pragma unroll
    for (int q = 0; q < 4; q++) {
        int d = tid + q*256;
        float y = xr[d] + ar[d];
        vals[q] = y; s += y; ss += y*y;
    }
#pragma unroll
    for (int o = 16; o > 0; o >>= 1) {
        s  += __shfl_xor_sync(0xffffffffu, s, o);
        ss += __shfl_xor_sync(0xffffffffu, ss, o);
    }
    if ((tid & 31) == 0) { shs[tid>>5] = s; shss[tid>>5] = ss; }
    __syncthreads();
    if (tid < 8) {
        float t1 = shs[tid], t2 = shss[tid];
#pragma unroll
        for (int o = 4; o > 0; o >>= 1) {
            t1 += __shfl_xor_sync(0xffu, t1, o);
            t2 += __shfl_xor_sync(0xffu, t2, o);
        }
        if (tid == 0) { shs[0] = t1; shss[0] = t2; }
    }
    __syncthreads();
    const float mu = shs[0] * (1.0f/DMODEL);
    const float var = shss[0] * (1.0f/DMODEL) - mu*mu;
    const float inv = rsqrtf(var + 1e-5f);

    float* orow = out + (size_t)n * DMODEL;
#pragma unroll
    for (int q = 0; q < 4; q++) {
        int d = tid + q*256;
        orow[d] = (vals[q] - mu) * inv * gamma[d] + beta[d];
    }
}

// ---------------- launch ---------------------------------------------------------
extern "C" void kernel_launch(void* const* d_in, const int* in_sizes, int n_in,
                              void* d_out, int out_size)
{
    (void)in_sizes; (void)n_in; (void)out_size;
    const float* x       = (const float*)d_in[0];
    const float* pos_emb = (const float*)d_in[1];
    const float* bu      = (const float*)d_in[2];
    const float* bv      = (const float*)d_in[3];
    const float* memory  = (const float*)d_in[4];
    const float* W_qkv   = (const float*)d_in[5];
    const float* W_rel   = (const float*)d_in[6];
    const float* W_o     = (const float*)d_in[7];
    const float* gamma   = (const float*)d_in[8];
    const float* beta    = (const float*)d_in[9];
    float* out = (float*)d_out;

    const int SM_BIG = 128*272 + 128*272 + 128*129*4;  // 135680 (modes 0,1,5)
    const int SM_AB  = 128*144 + 128*144 + 128*129*4;  // 102912 (mode 3)

    cudaFuncSetAttribute(gemm_tc<0>, cudaFuncAttributeMaxDynamicSharedMemorySize, SM_BIG);
    cudaFuncSetAttribute(gemm_tc<1>, cudaFuncAttributeMaxDynamicSharedMemorySize, SM_BIG);
    cudaFuncSetAttribute(gemm_tc<3>, cudaFuncAttributeMaxDynamicSharedMemorySize, SM_AB);
    cudaFuncSetAttribute(gemm_tc<5>, cudaFuncAttributeMaxDynamicSharedMemorySize, SM_BIG);

    conv_in<<<10240, 256>>>(memory, x, pos_emb);
    transpose_bf<<<dim3(96, 32), 256>>>(W_qkv, 0, 3072);
    transpose_bf<<<dim3(32, 32), 256>>>(W_rel, 1, 1024);
    transpose_bf<<<dim3(32, 32), 256>>>(W_o,   2, 1024);

    gemm_tc<0><<<dim3(24, 64),    256, SM_BIG>>>(bu, bv);            // QKV (dead tiles skipped, scale folded)
    gemm_tc<1><<<dim3(8, 16),     256, SM_BIG>>>(nullptr, nullptr);  // REL
    gemm_tc<3><<<dim3(16, 8, 64), 256, SM_AB>>>(nullptr, nullptr);   // BD -> shifted scaled bf16
    flash_attn<<<dim3(8, 64), 256>>>();                              // AC+softmax+PV fused
    gemm_tc<5><<<dim3(8, 32),     256, SM_BIG>>>(nullptr, nullptr);  // OUT
    ln_kernel<<<4096, 256>>>(x, gamma, beta, out);
}

// round 16
// speedup vs baseline: 1.5927x; 1.0028x over previous
#include <cuda_runtime.h>
#include <cuda_bf16.h>
#include <math.h>
#include <stdint.h>

#define SQ 1024
#define DMODEL 1024
// logits computed in log2 domain: fold 0.125*log2(e) into qu/qv at QKV epilogue
#define SCL2 0.18033688f

// ---------------- scratch (static device globals; allocation-free) -------------
__device__ __nv_bfloat16 c_bf  [(size_t)8192*1024];   // concat(memory,x), row n=t*4+b
__device__ __nv_bfloat16 pos_bf[(size_t)2048*1024];
__device__ __nv_bfloat16 wqkvT [(size_t)3072*1024];   // W_qkv^T
__device__ __nv_bfloat16 wrelT [(size_t)1024*1024];
__device__ __nv_bfloat16 woT   [(size_t)1024*1024];
__device__ __nv_bfloat16 g_qu  [(size_t)64*1024*64];  // [bh][i][dh]  (pre-scaled)
__device__ __nv_bfloat16 g_qv  [(size_t)64*1024*64];  //              (pre-scaled)
__device__ __nv_bfloat16 g_k   [(size_t)64*2048*64];  // [bh][t][dh]
__device__ __nv_bfloat16 g_vT  [(size_t)64*64*2048];  // [bh][dh][t]
__device__ __nv_bfloat16 g_r   [(size_t)16*2048*64];  // [h][p][dh]
__device__ __nv_bfloat16 g_BDs [(size_t)64*1024*2048];// pre-SHIFTED scaled BD, [bh][i][j] bf16
__device__ __nv_bfloat16 g_avec[(size_t)4096*1024];   // [i*4+b][h*64+dh]
__device__ float         g_aout[(size_t)4096*1024];

// ---------------- helpers -------------------------------------------------------
__device__ __forceinline__ uint32_t smem_u32(const void* p){
    uint32_t a;
    asm("{ .reg .u64 t; cvta.to.shared.u64 t, %1; cvt.u32.u64 %0, t; }" : "=r"(a) : "l"(p));
    return a;
}
__device__ __forceinline__ uint32_t pk2(float a, float b){
    return (uint32_t)__bfloat16_as_ushort(__float2bfloat16(a))
         | ((uint32_t)__bfloat16_as_ushort(__float2bfloat16(b)) << 16);
}
__device__ __forceinline__ float lo_bf(uint32_t u){
    return __bfloat162float(__ushort_as_bfloat16((unsigned short)(u & 0xffffu)));
}
__device__ __forceinline__ float hi_bf(uint32_t u){
    return __bfloat162float(__ushort_as_bfloat16((unsigned short)(u >> 16)));
}
__device__ __forceinline__ float ex2(float x){
    float y; asm("ex2.approx.f32 %0, %1;" : "=f"(y) : "f"(x)); return y;
}
__device__ __forceinline__ void ldm_x4(uint32_t* r, uint32_t addr){
    asm volatile("ldmatrix.sync.aligned.m8n8.x4.shared.b16 {%0,%1,%2,%3}, [%4];"
        : "=r"(r[0]), "=r"(r[1]), "=r"(r[2]), "=r"(r[3]) : "r"(addr));
}
__device__ __forceinline__ void mma16816(float* c, const uint32_t* a, const uint32_t* b){
    asm volatile("mma.sync.aligned.m16n8k16.row.col.f32.bf16.bf16.f32 "
        "{%0,%1,%2,%3}, {%4,%5,%6,%7}, {%8,%9}, {%0,%1,%2,%3};"
        : "+f"(c[0]), "+f"(c[1]), "+f"(c[2]), "+f"(c[3])
        : "r"(a[0]), "r"(a[1]), "r"(a[2]), "r"(a[3]), "r"(b[0]), "r"(b[1]));
}

// ---------------- prep kernels --------------------------------------------------
__global__ void __launch_bounds__(256) conv_in(const float* __restrict__ mem,
                                               const float* __restrict__ x,
                                               const float* __restrict__ pe){
    size_t n = blockIdx.x;
    const float* src; __nv_bfloat16* dst;
    if (n < 8192) {
        src = (n < 4096) ? (mem + n*1024) : (x + (n-4096)*1024);
        dst = c_bf + n*1024;
    } else {
        size_t m = n - 8192;
        src = pe + m*1024;
        dst = pos_bf + m*1024;
    }
#pragma unroll
    for (int q = 0; q < 4; q++){ int d = threadIdx.x + q*256; dst[d] = __float2bfloat16(src[d]); }
}
// transpose fp32 [1024][C] -> bf16 [C][1024]
__global__ void __launch_bounds__(256) transpose_bf(const float* __restrict__ src, int mode, int C){
    __shared__ float tile[32][33];
    __nv_bfloat16* dst = (mode == 0) ? wqkvT : (mode == 1) ? wrelT : woT;
    const int R = 1024;
    int c0 = blockIdx.x*32, r0 = blockIdx.y*32;
    int tx = threadIdx.x & 31, ty = threadIdx.x >> 5;
#pragma unroll
    for (int q = 0; q < 4; q++)
        tile[ty + q*8][tx] = src[(size_t)(r0 + ty + q*8)*C + c0 + tx];
    __syncthreads();
#pragma unroll
    for (int q = 0; q < 4; q++)
        dst[(size_t)(c0 + ty + q*8)*R + r0 + tx] = __float2bfloat16(tile[tx][ty + q*8]);
}

// ---------------- generic mma.sync GEMM, register-prefetch pipelined -------------
// MODE 0: QKV   c_bf(8192x1024) @ wqkvT^T  -> scatter qu/qv/k/vT (bf16)
// MODE 1: REL   pos_bf(2048x1024) @ wrelT^T -> g_r (bf16)
// MODE 3: BD    qv(1024x64) @ r^T(2048x64) per bh -> pre-shifted bf16 g_BDs
// MODE 5: OUT   avec(4096x1024) @ woT^T   -> g_aout (f32)
template<int MODE>
__global__ void __launch_bounds__(256) gemm_tc(const float* __restrict__ bu, const float* __restrict__ bv)
{
    constexpr int KC = (MODE == 3) ? 64 : 128;
    constexpr int NT = 128;
    constexpr int NF = NT / 32;
    constexpr int SA = KC*2 + 16;
    constexpr int ASZ = 128*SA;
    constexpr int BSZ = NT*SA;
    extern __shared__ char smem[];
    char* smB = smem + ASZ;
    float* stage = (float*)(smem + ASZ + BSZ);   // [128][NT+1]
    const uint32_t smA32 = smem_u32(smem);
    const uint32_t smB32 = smA32 + ASZ;

    const int tid = threadIdx.x;
    const int lane = tid & 31, wid = tid >> 5;
    const int wm = wid & 1, wn = wid >> 1;

    int m0, n0, bh = 0, h = 0, nchunks;
    if (MODE == 0)      { m0 = blockIdx.y*128; n0 = blockIdx.x*128;
                          if (n0 < 1024 && m0 + 128 <= 4096) return;   // dead q tiles
                          nchunks = 8; }
    else if (MODE == 1) { m0 = blockIdx.y*128; n0 = blockIdx.x*128; nchunks = 8; }
    else if (MODE == 3) { bh = blockIdx.z; h = bh & 15; m0 = blockIdx.y*128; n0 = blockIdx.x*128;
                          if (n0 + m0 <= 768) return; nchunks = 1; }
    else                { m0 = blockIdx.y*128; n0 = blockIdx.x*128; nchunks = 8; }

    constexpr int RQ = KC/8;
    constexpr int APT = 128*RQ/256;
    constexpr int BPT = NT*RQ/256;
    uint4 pa[APT], pb[BPT];

    auto ldg_chunk = [&](int ch){
        const int k0 = ch * KC;
#pragma unroll
        for (int qq = 0; qq < APT; qq++) {
            int idx = qq*256 + tid;
            int row = idx / RQ, q = idx % RQ;
            const __nv_bfloat16* ap;
            if      (MODE == 0) ap = c_bf   + (size_t)(m0+row)*1024 + k0;
            else if (MODE == 1) ap = pos_bf + (size_t)(m0+row)*1024 + k0;
            else if (MODE == 3) ap = g_qv + ((size_t)bh*1024 + m0+row)*64 + k0;
            else                ap = g_avec + (size_t)(m0+row)*1024 + k0;
            pa[qq] = *(const uint4*)(ap + q*8);
        }
#pragma unroll
        for (int qq = 0; qq < BPT; qq++) {
            int idx = qq*256 + tid;
            int row = idx / RQ, q = idx % RQ;
            const __nv_bfloat16* bp;
            if      (MODE == 0) bp = wqkvT + (size_t)(n0+row)*1024 + k0;
            else if (MODE == 1) bp = wrelT + (size_t)(n0+row)*1024 + k0;
            else if (MODE == 3) bp = g_r + ((size_t)h*2048 + n0+row)*64 + k0;
            else                bp = woT + (size_t)(n0+row)*1024 + k0;
            pb[qq] = *(const uint4*)(bp + q*8);
        }
    };

    float acc[4][NF][4] = {};

    ldg_chunk(0);
    for (int ch = 0; ch < nchunks; ch++) {
        // ---- STS phase: dump prefetched registers to smem ----
#pragma unroll
        for (int qq = 0; qq < APT; qq++) {
            int idx = qq*256 + tid;
            int row = idx / RQ, q = idx % RQ;
            *(uint4*)(smem + row*SA + q*16) = pa[qq];
        }
#pragma unroll
        for (int qq = 0; qq < BPT; qq++) {
            int idx = qq*256 + tid;
            int row = idx / RQ, q = idx % RQ;
            *(uint4*)(smB + row*SA + q*16) = pb[qq];
        }
        __syncthreads();
        if (ch + 1 < nchunks) ldg_chunk(ch + 1);
        // ---- MMA phase ----
#pragma unroll
        for (int ks = 0; ks < KC/16; ks++) {
            const int colb = ks*32 + (lane >> 4)*16;
            uint32_t af[4][4];
#pragma unroll
            for (int mf = 0; mf < 4; mf++) {
                int r = wm*64 + mf*16 + (lane & 15);
                ldm_x4(af[mf], smA32 + r*SA + colb);
            }
            uint32_t bfr[NF][2];
#pragma unroll
            for (int nf2 = 0; nf2 < NF/2; nf2++) {
                uint32_t t4[4];
                int r = wn*(NT/4) + nf2*16 + (lane & 15);
                ldm_x4(t4, smB32 + r*SA + colb);
                bfr[2*nf2][0]   = t4[0]; bfr[2*nf2][1]   = t4[2];
                bfr[2*nf2+1][0] = t4[1]; bfr[2*nf2+1][1] = t4[3];
            }
#pragma unroll
            for (int mf = 0; mf < 4; mf++)
#pragma unroll
                for (int nf = 0; nf < NF; nf++)
                    mma16816(acc[mf][nf], af[mf], bfr[nf]);
        }
        __syncthreads();
    }

    // ---- dump fragments to staged SMEM [128][NT+1] ----
#pragma unroll
    for (int mf = 0; mf < 4; mf++)
#pragma unroll
        for (int nf = 0; nf < NF; nf++) {
            int r0 = wm*64 + mf*16 + (lane >> 2);
            int c0 = wn*(NT/4) + nf*8 + (lane & 3)*2;
            stage[r0*(NT+1)+c0]       = acc[mf][nf][0];
            stage[r0*(NT+1)+c0+1]     = acc[mf][nf][1];
            stage[(r0+8)*(NT+1)+c0]   = acc[mf][nf][2];
            stage[(r0+8)*(NT+1)+c0+1] = acc[mf][nf][3];
        }
    __syncthreads();
    if (tid >= 128) return;

#define STG(r,c) stage[(r)*(NT+1)+(c)]

    if (MODE == 0) {
#pragma unroll
        for (int g = 0; g < 4; g++) {
            const int gc0 = n0 + g*32;
            const int which = gc0 >> 10;
            const int hc0 = gc0 & 1023;
            const int hh = hc0 >> 6, dh0 = hc0 & 63;
            const int n = m0 + tid, t = n >> 2, bb = n & 3;
            if (which == 0) {
                if (t >= 1024) {
                    uint32_t pu[16], pv[16];
#pragma unroll
                    for (int c = 0; c < 32; c += 2) {
                        float v0 = STG(tid, g*32+c), v1 = STG(tid, g*32+c+1);
                        pu[c>>1] = pk2((v0 + bu[hc0+c])*SCL2, (v1 + bu[hc0+c+1])*SCL2);
                        pv[c>>1] = pk2((v0 + bv[hc0+c])*SCL2, (v1 + bv[hc0+c+1])*SCL2);
                    }
                    size_t base = ((size_t)(bb*16+hh)*1024 + (t-1024))*64 + dh0;
#pragma unroll
                    for (int q = 0; q < 4; q++) {
                        *(uint4*)(g_qu + base + q*8) = make_uint4(pu[q*4], pu[q*4+1], pu[q*4+2], pu[q*4+3]);
                        *(uint4*)(g_qv + base + q*8) = make_uint4(pv[q*4], pv[q*4+1], pv[q*4+2], pv[q*4+3]);
                    }
                }
            } else if (which == 1) {
                uint32_t pk[16];
#pragma unroll
                for (int c = 0; c < 32; c += 2) pk[c>>1] = pk2(STG(tid, g*32+c), STG(tid, g*32+c+1));
                size_t base = ((size_t)(bb*16+hh)*2048 + t)*64 + dh0;
#pragma unroll
                for (int q = 0; q < 4; q++)
                    *(uint4*)(g_k + base + q*8) = make_uint4(pk[q*4], pk[q*4+1], pk[q*4+2], pk[q*4+3]);
            } else {
                const int c2 = tid & 31, sub = tid >> 5;
                const int t0 = m0 >> 2;
                uint32_t w[16];
#pragma unroll
                for (int tl = 0; tl < 32; tl += 2)
                    w[tl>>1] = pk2(STG(tl*4+sub, g*32+c2), STG((tl+1)*4+sub, g*32+c2));
                size_t base = ((size_t)(sub*16+hh)*64 + dh0 + c2)*2048 + t0;
#pragma unroll
                for (int q = 0; q < 4; q++)
                    *(uint4*)(g_vT + base + q*8) = make_uint4(w[q*4], w[q*4+1], w[q*4+2], w[q*4+3]);
            }
        }
    } else if (MODE == 1) {
#pragma unroll
        for (int g = 0; g < 4; g++) {
            const int gc0 = n0 + g*32;
            const int hh = gc0 >> 6, dh0 = gc0 & 63;
            uint32_t pk[16];
#pragma unroll
            for (int c = 0; c < 32; c += 2) pk[c>>1] = pk2(STG(tid, g*32+c), STG(tid, g*32+c+1));
            size_t base = ((size_t)hh*2048 + (m0+tid))*64 + dh0;
#pragma unroll
            for (int q = 0; q < 4; q++)
                *(uint4*)(g_r + base + q*8) = make_uint4(pk[q*4], pk[q*4+1], pk[q*4+2], pk[q*4+3]);
        }
    } else if (MODE == 3) {
        // pre-shifted BD store: g_BDs[bh][i][j] = BD[i][p], j = p + i - 1023
        const int i = m0 + tid;
        __nv_bfloat16* dst = g_BDs + ((size_t)bh*1024 + i)*2048;
#pragma unroll
        for (int g = 0; g < 4; g++) {
            const int gc0 = n0 + g*32;
            const int jbase = gc0 + i - 1023;
            float v[32];
#pragma unroll
            for (int c = 0; c < 32; c++) v[c] = STG(tid, g*32+c);
            if (!(jbase & 1)) {
#pragma unroll
                for (int c = 0; c < 32; c += 2) {
                    int j = jbase + c;
                    if (j >= 0) *(uint32_t*)(dst + j) = pk2(v[c], v[c+1]);
                }
            } else {
                if (jbase >= 0) dst[jbase] = __float2bfloat16(v[0]);
#pragma unroll
                for (int c = 1; c < 31; c += 2) {
                    int j = jbase + c;
                    if (j >= 0) *(uint32_t*)(dst + j) = pk2(v[c], v[c+1]);
                }
                if (jbase + 31 >= 0) dst[jbase + 31] = __float2bfloat16(v[31]);
            }
        }
    } else {
        float* dst = g_aout + (size_t)(m0+tid)*1024;
#pragma unroll
        for (int g = 0; g < 4; g++) {
            const int gc0 = n0 + g*32;
#pragma unroll
            for (int c = 0; c < 32; c += 4)
                *(float4*)(dst + gc0 + c) = make_float4(STG(tid, g*32+c),   STG(tid, g*32+c+1),
                                                        STG(tid, g*32+c+2), STG(tid, g*32+c+3));
        }
    }
#undef STG
}

// ---------------- fused flash attention, K/V register-prefetch, lean regs --------
// grid (8 i-tiles, 64 bh), 256 threads. Warp w owns query rows [16w, 16w+16).
// Logits are in log2 domain (scale folded into qu/qv); exp -> ex2.
__global__ void __launch_bounds__(256, 1) flash_attn()
{
    __shared__ __align__(16) char smK[128*144];   // K tile [128 j][64 k], also qu tile at start
    __shared__ __align__(16) char smV[64*272];    // VT tile [64 dh][128 j]
    const uint32_t smK32 = smem_u32(smK);
    const uint32_t smV32 = smem_u32(smV);

    const int bh = blockIdx.y, b = bh >> 4, h = bh & 15;
    const int m0 = (7 - blockIdx.x) * 128;        // longest-work-first
    const int tid = threadIdx.x, lane = tid & 31, w = tid >> 5;
    const int r0 = w * 16;

    // ---- qu tile -> smem -> A fragments (held in regs for all j-tiles) ----
    {
        const __nv_bfloat16* qp = g_qu + ((size_t)bh*1024 + m0)*64;
#pragma unroll
        for (int q4 = 0; q4 < 4; q4++) {
            int idx = q4*256 + tid; int row = idx >> 3, q = idx & 7;
            *(uint4*)(smK + row*144 + q*16) = *(const uint4*)(qp + (size_t)row*64 + q*8);
        }
    }
    __syncthreads();
    uint32_t af[4][4];
#pragma unroll
    for (int ks = 0; ks < 4; ks++)
        ldm_x4(af[ks], smK32 + (r0 + (lane & 15))*144 + ks*32 + (lane >> 4)*16);
    __syncthreads();

    uint4 pkr[4], pvr[4];
    auto ldg_kv = [&](int jt){
        const int j0n = jt * 128;
        const __nv_bfloat16* kp = g_k + ((size_t)bh*2048 + j0n)*64;
#pragma unroll
        for (int q4 = 0; q4 < 4; q4++) {
            int idx = q4*256 + tid; int row = idx >> 3, q = idx & 7;
            pkr[q4] = *(const uint4*)(kp + (size_t)row*64 + q*8);
        }
        const __nv_bfloat16* vp = g_vT + ((size_t)bh*64)*2048 + j0n;
#pragma unroll
        for (int q4 = 0; q4 < 4; q4++) {
            int idx = q4*256 + tid; int row = idx >> 4, q = idx & 15;
            pvr[q4] = *(const uint4*)(vp + (size_t)row*2048 + q*8);
        }
    };

    float mrow0 = -1e30f, mrow1 = -1e30f, lrow0 = 0.f, lrow1 = 0.f;
    float oacc[8][4] = {};
    const int ia = m0 + r0 + (lane >> 2);         // row A; row B = ia + 8
    const uint32_t* bdr0 = (const uint32_t*)(g_BDs + ((size_t)bh*1024 + ia)*2048) + (lane & 3);
    const uint32_t* bdr1 = (const uint32_t*)(g_BDs + ((size_t)bh*1024 + ia + 8)*2048) + (lane & 3);

    const int ntiles = m0/128 + 9;
    ldg_kv(0);
    for (int jt = 0; jt < ntiles; jt++) {
        const int j0 = jt * 128;
        // ---- STS phase: dump prefetched K/V regs to smem ----
#pragma unroll
        for (int q4 = 0; q4 < 4; q4++) {
            int idx = q4*256 + tid; int row = idx >> 3, q = idx & 7;
            *(uint4*)(smK + row*144 + q*16) = pkr[q4];
        }
#pragma unroll
        for (int q4 = 0; q4 < 4; q4++) {
            int idx = q4*256 + tid; int row = idx >> 4, q = idx & 15;
            *(uint4*)(smV + row*272 + q*16) = pvr[q4];
        }
        __syncthreads();
        if (jt + 1 < ntiles) ldg_kv(jt + 1);

        // ---- S = qu * K^T  (16 rows x 128 cols per warp), ldm feeds MMA directly --
        float sacc[16][4] = {};
#pragma unroll
        for (int ks = 0; ks < 4; ks++) {
#pragma unroll
            for (int nb = 0; nb < 8; nb++) {
                uint32_t t4[4];
                ldm_x4(t4, smK32 + (nb*16 + (lane & 15))*144 + ks*32 + (lane >> 4)*16);
                uint32_t b0[2] = { t4[0], t4[2] };
                uint32_t b1[2] = { t4[1], t4[3] };
                mma16816(sacc[2*nb],   af[ks], b0);
                mma16816(sacc[2*nb+1], af[ks], b1);
            }
        }

        // ---- logits (log2 domain): + shifted BD (direct loads), causal mask ----
        const uint32_t* b0p = bdr0 + (j0 >> 1);
        const uint32_t* b1p = bdr1 + (j0 >> 1);
        float tmax0 = -1e30f, tmax1 = -1e30f;
#pragma unroll
        for (int nf = 0; nf < 16; nf++) {
            int j = j0 + nf*8 + (lane & 3)*2;
            uint32_t bdA = b0p[nf*4];
            uint32_t bdB = b1p[nf*4];
            float a0 = sacc[nf][0] + lo_bf(bdA);
            float a1 = sacc[nf][1] + hi_bf(bdA);
            float b0 = sacc[nf][2] + lo_bf(bdB);
            float b1 = sacc[nf][3] + hi_bf(bdB);
            sacc[nf][0] = (j     <= ia + 1024)     ? a0 : -1e30f;
            sacc[nf][1] = (j + 1 <= ia + 1024)     ? a1 : -1e30f;
            sacc[nf][2] = (j     <= ia + 8 + 1024) ? b0 : -1e30f;
            sacc[nf][3] = (j + 1 <= ia + 8 + 1024) ? b1 : -1e30f;
            tmax0 = fmaxf(tmax0, fmaxf(sacc[nf][0], sacc[nf][1]));
            tmax1 = fmaxf(tmax1, fmaxf(sacc[nf][2], sacc[nf][3]));
        }
        tmax0 = fmaxf(tmax0, __shfl_xor_sync(0xffffffffu, tmax0, 1));
        tmax0 = fmaxf(tmax0, __shfl_xor_sync(0xffffffffu, tmax0, 2));
        tmax1 = fmaxf(tmax1, __shfl_xor_sync(0xffffffffu, tmax1, 1));
        tmax1 = fmaxf(tmax1, __shfl_xor_sync(0xffffffffu, tmax1, 2));

        const float mnew0 = fmaxf(mrow0, tmax0), mnew1 = fmaxf(mrow1, tmax1);
        const float f0 = ex2(mrow0 - mnew0), f1 = ex2(mrow1 - mnew1);
        mrow0 = mnew0; mrow1 = mnew1;
        lrow0 *= f0; lrow1 *= f1;
#pragma unroll
        for (int nf = 0; nf < 8; nf++) {
            oacc[nf][0] *= f0; oacc[nf][1] *= f0;
            oacc[nf][2] *= f1; oacc[nf][3] *= f1;
        }

        // ---- P = 2^(S - m), pack acc frags -> A frags ----
        uint32_t pf[8][4];
        float s0 = 0.f, s1 = 0.f;
#pragma unroll
        for (int kf = 0; kf < 8; kf++) {
            float e00 = ex2(sacc[2*kf][0]   - mnew0), e01 = ex2(sacc[2*kf][1]   - mnew0);
            float e02 = ex2(sacc[2*kf][2]   - mnew1), e03 = ex2(sacc[2*kf][3]   - mnew1);
            float e10 = ex2(sacc[2*kf+1][0] - mnew0), e11 = ex2(sacc[2*kf+1][1] - mnew0);
            float e12 = ex2(sacc[2*kf+1][2] - mnew1), e13 = ex2(sacc[2*kf+1][3] - mnew1);
            s0 += e00 + e01 + e10 + e11;
            s1 += e02 + e03 + e12 + e13;
            pf[kf][0] = pk2(e00, e01);
            pf[kf][1] = pk2(e02, e03);
            pf[kf][2] = pk2(e10, e11);
            pf[kf][3] = pk2(e12, e13);
        }
        lrow0 += s0; lrow1 += s1;

        // ---- O += P * V, ldm feeds MMA directly ----
#pragma unroll
        for (int kf = 0; kf < 8; kf++) {
#pragma unroll
            for (int nb = 0; nb < 4; nb++) {
                uint32_t t4[4];
                ldm_x4(t4, smV32 + (nb*16 + (lane & 15))*272 + kf*32 + (lane >> 4)*16);
                uint32_t b0[2] = { t4[0], t4[2] };
                uint32_t b1[2] = { t4[1], t4[3] };
                mma16816(oacc[2*nb],   pf[kf], b0);
                mma16816(oacc[2*nb+1], pf[kf], b1);
            }
        }
        __syncthreads();
    }

    // ---- finalize: O /= l, write bf16 to g_avec ----
    lrow0 += __shfl_xor_sync(0xffffffffu, lrow0, 1);
    lrow0 += __shfl_xor_sync(0xffffffffu, lrow0, 2);
    lrow1 += __shfl_xor_sync(0xffffffffu, lrow1, 1);
    lrow1 += __shfl_xor_sync(0xffffffffu, lrow1, 2);
    const float inv0 = 1.f / lrow0, inv1 = 1.f / lrow1;

    __nv_bfloat16* d0 = g_avec + ((size_t)ia*4 + b)*1024 + h*64;
    __nv_bfloat16* d1 = g_avec + ((size_t)(ia+8)*4 + b)*1024 + h*64;
#pragma unroll
    for (int nf = 0; nf < 8; nf++) {
        int c = nf*8 + (lane & 3)*2;
        *(uint32_t*)(d0 + c) = pk2(oacc[nf][0]*inv0, oacc[nf][1]*inv0);
        *(uint32_t*)(d1 + c) = pk2(oacc[nf][2]*inv1, oacc[nf][3]*inv1);
    }
}

// ---------------- residual + LayerNorm ------------------------------------------
__global__ void __launch_bounds__(256) ln_kernel(
    const float* __restrict__ x, const float* __restrict__ gamma,
    const float* __restrict__ beta, float* __restrict__ out)
{
    __shared__ float shs[8], shss[8];
    const int n = blockIdx.x;
    const int tid = threadIdx.x;
    const float* xr = x + (size_t)n * DMODEL;
    const float* ar = g_aout + (size_t)n * DMODEL;

    float vals[4];
    float s = 0.f, ss = 0.f;
#pragma unroll
    for (int q = 0; q < 4; q++) {
        int d = tid + q*256;
        float y = xr[d] + ar[d];
        vals[q] = y; s += y; ss += y*y;
    }
#pragma unroll
    for (int o = 16; o > 0; o >>= 1) {
        s  += __shfl_xor_sync(0xffffffffu, s, o);
        ss += __shfl_xor_sync(0xffffffffu, ss, o);
    }
    if ((tid & 31) == 0) { shs[tid>>5] = s; shss[tid>>5] = ss; }
    __syncthreads();
    if (tid < 8) {
        float t1 = shs[tid], t2 = shss[tid];
#pragma unroll
        for (int o = 4; o > 0; o >>= 1) {
            t1 += __shfl_xor_sync(0xffu, t1, o);
            t2 += __shfl_xor_sync(0xffu, t2, o);
        }
        if (tid == 0) { shs[0] = t1; shss[0] = t2; }
    }
    __syncthreads();
    const float mu = shs[0] * (1.0f/DMODEL);
    const float var = shss[0] * (1.0f/DMODEL) - mu*mu;
    const float inv = rsqrtf(var + 1e-5f);

    float* orow = out + (size_t)n * DMODEL;
#pragma unroll
    for (int q = 0; q < 4; q++) {
        int d = tid + q*256;
        orow[d] = (vals[q] - mu) * inv * gamma[d] + beta[d];
    }
}

// ---------------- launch ---------------------------------------------------------
extern "C" void kernel_launch(void* const* d_in, const int* in_sizes, int n_in,
                              void* d_out, int out_size)
{
    (void)in_sizes; (void)n_in; (void)out_size;
    const float* x       = (const float*)d_in[0];
    const float* pos_emb = (const float*)d_in[1];
    const float* bu      = (const float*)d_in[2];
    const float* bv      = (const float*)d_in[3];
    const float* memory  = (const float*)d_in[4];
    const float* W_qkv   = (const float*)d_in[5];
    const float* W_rel   = (const float*)d_in[6];
    const float* W_o     = (const float*)d_in[7];
    const float* gamma   = (const float*)d_in[8];
    const float* beta    = (const float*)d_in[9];
    float* out = (float*)d_out;

    const int SM_BIG = 128*272 + 128*272 + 128*129*4;  // 135680 (modes 0,1,5)
    const int SM_AB  = 128*144 + 128*144 + 128*129*4;  // 102912 (mode 3)

    cudaFuncSetAttribute(gemm_tc<0>, cudaFuncAttributeMaxDynamicSharedMemorySize, SM_BIG);
    cudaFuncSetAttribute(gemm_tc<1>, cudaFuncAttributeMaxDynamicSharedMemorySize, SM_BIG);
    cudaFuncSetAttribute(gemm_tc<3>, cudaFuncAttributeMaxDynamicSharedMemorySize, SM_AB);
    cudaFuncSetAttribute(gemm_tc<5>, cudaFuncAttributeMaxDynamicSharedMemorySize, SM_BIG);

    conv_in<<<10240, 256>>>(memory, x, pos_emb);
    transpose_bf<<<dim3(96, 32), 256>>>(W_qkv, 0, 3072);
    transpose_bf<<<dim3(32, 32), 256>>>(W_rel, 1, 1024);
    transpose_bf<<<dim3(32, 32), 256>>>(W_o,   2, 1024);

    gemm_tc<0><<<dim3(24, 64),    256, SM_BIG>>>(bu, bv);            // QKV (dead tiles skipped, scale folded)
    gemm_tc<1><<<dim3(8, 16),     256, SM_BIG>>>(nullptr, nullptr);  // REL
    gemm_tc<3><<<dim3(16, 8, 64), 256, SM_AB>>>(nullptr, nullptr);   // BD -> shifted scaled bf16
    flash_attn<<<dim3(8, 64), 256>>>();                              // AC+softmax+PV fused
    gemm_tc<5><<<dim3(8, 32),     256, SM_BIG>>>(nullptr, nullptr);  // OUT
    ln_kernel<<<4096, 256>>>(x, gamma, beta, out);
}

// round 17
// speedup vs baseline: 1.6115x; 1.0118x over previous
#include <cuda_runtime.h>
#include <cuda_bf16.h>
#include <math.h>
#include <stdint.h>

#define SQ 1024
#define DMODEL 1024
// logits computed in log2 domain: fold 0.125*log2(e) into qu/qv at QKV epilogue
#define SCL2 0.18033688f

// ---------------- scratch (static device globals; allocation-free) -------------
__device__ __nv_bfloat16 c_bf  [(size_t)8192*1024];   // concat(memory,x), row n=t*4+b
__device__ __nv_bfloat16 pos_bf[(size_t)2048*1024];
__device__ __nv_bfloat16 wqkvT [(size_t)3072*1024];   // W_qkv^T
__device__ __nv_bfloat16 wrelT [(size_t)1024*1024];
__device__ __nv_bfloat16 woT   [(size_t)1024*1024];
__device__ __nv_bfloat16 g_qu  [(size_t)64*1024*64];  // [bh][i][dh]  (pre-scaled)
__device__ __nv_bfloat16 g_qv  [(size_t)64*1024*64];  //              (pre-scaled)
__device__ __nv_bfloat16 g_k   [(size_t)64*2048*64];  // [bh][t][dh]
__device__ __nv_bfloat16 g_vT  [(size_t)64*64*2048];  // [bh][dh][t]
__device__ __nv_bfloat16 g_r   [(size_t)16*2048*64];  // [h][p][dh]
__device__ __nv_bfloat16 g_BDs [(size_t)64*1024*2048];// pre-SHIFTED scaled BD, [bh][i][j] bf16
__device__ __nv_bfloat16 g_avec[(size_t)4096*1024];   // [i*4+b][h*64+dh]
__device__ float         g_aout[(size_t)4096*1024];

// ---------------- helpers -------------------------------------------------------
__device__ __forceinline__ uint32_t smem_u32(const void* p){
    uint32_t a;
    asm("{ .reg .u64 t; cvta.to.shared.u64 t, %1; cvt.u32.u64 %0, t; }" : "=r"(a) : "l"(p));
    return a;
}
__device__ __forceinline__ uint32_t pk2(float a, float b){
    return (uint32_t)__bfloat16_as_ushort(__float2bfloat16(a))
         | ((uint32_t)__bfloat16_as_ushort(__float2bfloat16(b)) << 16);
}
__device__ __forceinline__ float lo_bf(uint32_t u){
    return __bfloat162float(__ushort_as_bfloat16((unsigned short)(u & 0xffffu)));
}
__device__ __forceinline__ float hi_bf(uint32_t u){
    return __bfloat162float(__ushort_as_bfloat16((unsigned short)(u >> 16)));
}
__device__ __forceinline__ float ex2(float x){
    float y; asm("ex2.approx.f32 %0, %1;" : "=f"(y) : "f"(x)); return y;
}
__device__ __forceinline__ void ldm_x4(uint32_t* r, uint32_t addr){
    asm volatile("ldmatrix.sync.aligned.m8n8.x4.shared.b16 {%0,%1,%2,%3}, [%4];"
        : "=r"(r[0]), "=r"(r[1]), "=r"(r[2]), "=r"(r[3]) : "r"(addr));
}
__device__ __forceinline__ void mma16816(float* c, const uint32_t* a, const uint32_t* b){
    asm volatile("mma.sync.aligned.m16n8k16.row.col.f32.bf16.bf16.f32 "
        "{%0,%1,%2,%3}, {%4,%5,%6,%7}, {%8,%9}, {%0,%1,%2,%3};"
        : "+f"(c[0]), "+f"(c[1]), "+f"(c[2]), "+f"(c[3])
        : "r"(a[0]), "r"(a[1]), "r"(a[2]), "r"(a[3]), "r"(b[0]), "r"(b[1]));
}

// ---------------- prep kernels --------------------------------------------------
__global__ void __launch_bounds__(256) conv_in(const float* __restrict__ mem,
                                               const float* __restrict__ x,
                                               const float* __restrict__ pe){
    size_t n = blockIdx.x;
    const float* src; __nv_bfloat16* dst;
    if (n < 8192) {
        src = (n < 4096) ? (mem + n*1024) : (x + (n-4096)*1024);
        dst = c_bf + n*1024;
    } else {
        size_t m = n - 8192;
        src = pe + m*1024;
        dst = pos_bf + m*1024;
    }
#pragma unroll
    for (int q = 0; q < 4; q++){ int d = threadIdx.x + q*256; dst[d] = __float2bfloat16(src[d]); }
}
// transpose fp32 [1024][C] -> bf16 [C][1024]
__global__ void __launch_bounds__(256) transpose_bf(const float* __restrict__ src, int mode, int C){
    __shared__ float tile[32][33];
    __nv_bfloat16* dst = (mode == 0) ? wqkvT : (mode == 1) ? wrelT : woT;
    const int R = 1024;
    int c0 = blockIdx.x*32, r0 = blockIdx.y*32;
    int tx = threadIdx.x & 31, ty = threadIdx.x >> 5;
#pragma unroll
    for (int q = 0; q < 4; q++)
        tile[ty + q*8][tx] = src[(size_t)(r0 + ty + q*8)*C + c0 + tx];
    __syncthreads();
#pragma unroll
    for (int q = 0; q < 4; q++)
        dst[(size_t)(c0 + ty + q*8)*R + r0 + tx] = __float2bfloat16(tile[tx][ty + q*8]);
}

// ---------------- generic mma.sync GEMM, register-prefetch pipelined -------------
// MODE 0: QKV   c_bf(8192x1024) @ wqkvT^T  -> scatter qu/qv/k/vT (bf16)
// MODE 1: REL   pos_bf(2048x1024) @ wrelT^T -> g_r (bf16)
// MODE 3: BD    qv(1024x64) @ r^T(2048x64) per bh -> pre-shifted bf16 g_BDs
// MODE 5: OUT   avec(4096x1024) @ woT^T   -> g_aout (f32)
// stage buffer ALIASES the A/B tiles (live only after the mainloop's trailing
// barrier) -> dyn smem ~66-70KB. Mode 3 (low reg pressure) runs 2 CTAs/SM.
template<int MODE>
__global__ void __launch_bounds__(256, MODE == 3 ? 2 : 1) gemm_tc(
    const float* __restrict__ bu, const float* __restrict__ bv)
{
    constexpr int KC = (MODE == 3) ? 64 : 128;
    constexpr int NT = 128;
    constexpr int NF = NT / 32;
    constexpr int SA = KC*2 + 16;
    constexpr int ASZ = 128*SA;
    constexpr int BSZ = NT*SA;
    extern __shared__ char smem[];
    char* smB = smem + ASZ;
    float* stage = (float*)smem;                 // aliases A/B tiles (post-mainloop only)
    const uint32_t smA32 = smem_u32(smem);
    const uint32_t smB32 = smA32 + ASZ;

    const int tid = threadIdx.x;
    const int lane = tid & 31, wid = tid >> 5;
    const int wm = wid & 1, wn = wid >> 1;

    int m0, n0, bh = 0, h = 0, nchunks;
    if (MODE == 0)      { m0 = blockIdx.y*128; n0 = blockIdx.x*128;
                          if (n0 < 1024 && m0 + 128 <= 4096) return;   // dead q tiles
                          nchunks = 8; }
    else if (MODE == 1) { m0 = blockIdx.y*128; n0 = blockIdx.x*128; nchunks = 8; }
    else if (MODE == 3) { bh = blockIdx.z; h = bh & 15; m0 = blockIdx.y*128; n0 = blockIdx.x*128;
                          if (n0 + m0 <= 768) return; nchunks = 1; }
    else                { m0 = blockIdx.y*128; n0 = blockIdx.x*128; nchunks = 8; }

    constexpr int RQ = KC/8;
    constexpr int APT = 128*RQ/256;
    constexpr int BPT = NT*RQ/256;
    uint4 pa[APT], pb[BPT];

    auto ldg_chunk = [&](int ch){
        const int k0 = ch * KC;
#pragma unroll
        for (int qq = 0; qq < APT; qq++) {
            int idx = qq*256 + tid;
            int row = idx / RQ, q = idx % RQ;
            const __nv_bfloat16* ap;
            if      (MODE == 0) ap = c_bf   + (size_t)(m0+row)*1024 + k0;
            else if (MODE == 1) ap = pos_bf + (size_t)(m0+row)*1024 + k0;
            else if (MODE == 3) ap = g_qv + ((size_t)bh*1024 + m0+row)*64 + k0;
            else                ap = g_avec + (size_t)(m0+row)*1024 + k0;
            pa[qq] = *(const uint4*)(ap + q*8);
        }
#pragma unroll
        for (int qq = 0; qq < BPT; qq++) {
            int idx = qq*256 + tid;
            int row = idx / RQ, q = idx % RQ;
            const __nv_bfloat16* bp;
            if      (MODE == 0) bp = wqkvT + (size_t)(n0+row)*1024 + k0;
            else if (MODE == 1) bp = wrelT + (size_t)(n0+row)*1024 + k0;
            else if (MODE == 3) bp = g_r + ((size_t)h*2048 + n0+row)*64 + k0;
            else                bp = woT + (size_t)(n0+row)*1024 + k0;
            pb[qq] = *(const uint4*)(bp + q*8);
        }
    };

    float acc[4][NF][4] = {};

    ldg_chunk(0);
    for (int ch = 0; ch < nchunks; ch++) {
        // ---- STS phase: dump prefetched registers to smem ----
#pragma unroll
        for (int qq = 0; qq < APT; qq++) {
            int idx = qq*256 + tid;
            int row = idx / RQ, q = idx % RQ;
            *(uint4*)(smem + row*SA + q*16) = pa[qq];
        }
#pragma unroll
        for (int qq = 0; qq < BPT; qq++) {
            int idx = qq*256 + tid;
            int row = idx / RQ, q = idx % RQ;
            *(uint4*)(smB + row*SA + q*16) = pb[qq];
        }
        __syncthreads();
        if (ch + 1 < nchunks) ldg_chunk(ch + 1);
        // ---- MMA phase ----
#pragma unroll
        for (int ks = 0; ks < KC/16; ks++) {
            const int colb = ks*32 + (lane >> 4)*16;
            uint32_t af[4][4];
#pragma unroll
            for (int mf = 0; mf < 4; mf++) {
                int r = wm*64 + mf*16 + (lane & 15);
                ldm_x4(af[mf], smA32 + r*SA + colb);
            }
            uint32_t bfr[NF][2];
#pragma unroll
            for (int nf2 = 0; nf2 < NF/2; nf2++) {
                uint32_t t4[4];
                int r = wn*(NT/4) + nf2*16 + (lane & 15);
                ldm_x4(t4, smB32 + r*SA + colb);
                bfr[2*nf2][0]   = t4[0]; bfr[2*nf2][1]   = t4[2];
                bfr[2*nf2+1][0] = t4[1]; bfr[2*nf2+1][1] = t4[3];
            }
#pragma unroll
            for (int mf = 0; mf < 4; mf++)
#pragma unroll
                for (int nf = 0; nf < NF; nf++)
                    mma16816(acc[mf][nf], af[mf], bfr[nf]);
        }
        __syncthreads();
    }

    // ---- dump fragments to staged SMEM [128][NT+1] (aliases A/B tiles) ----
#pragma unroll
    for (int mf = 0; mf < 4; mf++)
#pragma unroll
        for (int nf = 0; nf < NF; nf++) {
            int r0 = wm*64 + mf*16 + (lane >> 2);
            int c0 = wn*(NT/4) + nf*8 + (lane & 3)*2;
            stage[r0*(NT+1)+c0]       = acc[mf][nf][0];
            stage[r0*(NT+1)+c0+1]     = acc[mf][nf][1];
            stage[(r0+8)*(NT+1)+c0]   = acc[mf][nf][2];
            stage[(r0+8)*(NT+1)+c0+1] = acc[mf][nf][3];
        }
    __syncthreads();
    if (tid >= 128) return;

#define STG(r,c) stage[(r)*(NT+1)+(c)]

    if (MODE == 0) {
#pragma unroll
        for (int g = 0; g < 4; g++) {
            const int gc0 = n0 + g*32;
            const int which = gc0 >> 10;
            const int hc0 = gc0 & 1023;
            const int hh = hc0 >> 6, dh0 = hc0 & 63;
            const int n = m0 + tid, t = n >> 2, bb = n & 3;
            if (which == 0) {
                if (t >= 1024) {
                    uint32_t pu[16], pv[16];
#pragma unroll
                    for (int c = 0; c < 32; c += 2) {
                        float v0 = STG(tid, g*32+c), v1 = STG(tid, g*32+c+1);
                        pu[c>>1] = pk2((v0 + bu[hc0+c])*SCL2, (v1 + bu[hc0+c+1])*SCL2);
                        pv[c>>1] = pk2((v0 + bv[hc0+c])*SCL2, (v1 + bv[hc0+c+1])*SCL2);
                    }
                    size_t base = ((size_t)(bb*16+hh)*1024 + (t-1024))*64 + dh0;
#pragma unroll
                    for (int q = 0; q < 4; q++) {
                        *(uint4*)(g_qu + base + q*8) = make_uint4(pu[q*4], pu[q*4+1], pu[q*4+2], pu[q*4+3]);
                        *(uint4*)(g_qv + base + q*8) = make_uint4(pv[q*4], pv[q*4+1], pv[q*4+2], pv[q*4+3]);
                    }
                }
            } else if (which == 1) {
                uint32_t pk[16];
#pragma unroll
                for (int c = 0; c < 32; c += 2) pk[c>>1] = pk2(STG(tid, g*32+c), STG(tid, g*32+c+1));
                size_t base = ((size_t)(bb*16+hh)*2048 + t)*64 + dh0;
#pragma unroll
                for (int q = 0; q < 4; q++)
                    *(uint4*)(g_k + base + q*8) = make_uint4(pk[q*4], pk[q*4+1], pk[q*4+2], pk[q*4+3]);
            } else {
                const int c2 = tid & 31, sub = tid >> 5;
                const int t0 = m0 >> 2;
                uint32_t w[16];
#pragma unroll
                for (int tl = 0; tl < 32; tl += 2)
                    w[tl>>1] = pk2(STG(tl*4+sub, g*32+c2), STG((tl+1)*4+sub, g*32+c2));
                size_t base = ((size_t)(sub*16+hh)*64 + dh0 + c2)*2048 + t0;
#pragma unroll
                for (int q = 0; q < 4; q++)
                    *(uint4*)(g_vT + base + q*8) = make_uint4(w[q*4], w[q*4+1], w[q*4+2], w[q*4+3]);
            }
        }
    } else if (MODE == 1) {
#pragma unroll
        for (int g = 0; g < 4; g++) {
            const int gc0 = n0 + g*32;
            const int hh = gc0 >> 6, dh0 = gc0 & 63;
            uint32_t pk[16];
#pragma unroll
            for (int c = 0; c < 32; c += 2) pk[c>>1] = pk2(STG(tid, g*32+c), STG(tid, g*32+c+1));
            size_t base = ((size_t)hh*2048 + (m0+tid))*64 + dh0;
#pragma unroll
            for (int q = 0; q < 4; q++)
                *(uint4*)(g_r + base + q*8) = make_uint4(pk[q*4], pk[q*4+1], pk[q*4+2], pk[q*4+3]);
        }
    } else if (MODE == 3) {
        // pre-shifted BD store: g_BDs[bh][i][j] = BD[i][p], j = p + i - 1023
        const int i = m0 + tid;
        __nv_bfloat16* dst = g_BDs + ((size_t)bh*1024 + i)*2048;
#pragma unroll
        for (int g = 0; g < 4; g++) {
            const int gc0 = n0 + g*32;
            const int jbase = gc0 + i - 1023;
            float v[32];
#pragma unroll
            for (int c = 0; c < 32; c++) v[c] = STG(tid, g*32+c);
            if (!(jbase & 1)) {
#pragma unroll
                for (int c = 0; c < 32; c += 2) {
                    int j = jbase + c;
                    if (j >= 0) *(uint32_t*)(dst + j) = pk2(v[c], v[c+1]);
                }
            } else {
                if (jbase >= 0) dst[jbase] = __float2bfloat16(v[0]);
#pragma unroll
                for (int c = 1; c < 31; c += 2) {
                    int j = jbase + c;
                    if (j >= 0) *(uint32_t*)(dst + j) = pk2(v[c], v[c+1]);
                }
                if (jbase + 31 >= 0) dst[jbase + 31] = __float2bfloat16(v[31]);
            }
        }
    } else {
        float* dst = g_aout + (size_t)(m0+tid)*1024;
#pragma unroll
        for (int g = 0; g < 4; g++) {
            const int gc0 = n0 + g*32;
#pragma unroll
            for (int c = 0; c < 32; c += 4)
                *(float4*)(dst + gc0 + c) = make_float4(STG(tid, g*32+c),   STG(tid, g*32+c+1),
                                                        STG(tid, g*32+c+2), STG(tid, g*32+c+3));
        }
    }
#undef STG
}

// ---------------- fused flash attention, K/V register-prefetch, lean regs --------
// grid (8 i-tiles, 64 bh), 256 threads. Warp w owns query rows [16w, 16w+16).
// Logits are in log2 domain (scale folded into qu/qv); exp -> ex2.
__global__ void __launch_bounds__(256, 1) flash_attn()
{
    __shared__ __align__(16) char smK[128*144];   // K tile [128 j][64 k], also qu tile at start
    __shared__ __align__(16) char smV[64*272];    // VT tile [64 dh][128 j]
    const uint32_t smK32 = smem_u32(smK);
    const uint32_t smV32 = smem_u32(smV);

    const int bh = blockIdx.y, b = bh >> 4, h = bh & 15;
    const int m0 = (7 - blockIdx.x) * 128;        // longest-work-first
    const int tid = threadIdx.x, lane = tid & 31, w = tid >> 5;
    const int r0 = w * 16;

    // ---- qu tile -> smem -> A fragments (held in regs for all j-tiles) ----
    {
        const __nv_bfloat16* qp = g_qu + ((size_t)bh*1024 + m0)*64;
#pragma unroll
        for (int q4 = 0; q4 < 4; q4++) {
            int idx = q4*256 + tid; int row = idx >> 3, q = idx & 7;
            *(uint4*)(smK + row*144 + q*16) = *(const uint4*)(qp + (size_t)row*64 + q*8);
        }
    }
    __syncthreads();
    uint32_t af[4][4];
#pragma unroll
    for (int ks = 0; ks < 4; ks++)
        ldm_x4(af[ks], smK32 + (r0 + (lane & 15))*144 + ks*32 + (lane >> 4)*16);
    __syncthreads();

    uint4 pkr[4], pvr[4];
    auto ldg_kv = [&](int jt){
        const int j0n = jt * 128;
        const __nv_bfloat16* kp = g_k + ((size_t)bh*2048 + j0n)*64;
#pragma unroll
        for (int q4 = 0; q4 < 4; q4++) {
            int idx = q4*256 + tid; int row = idx >> 3, q = idx & 7;
            pkr[q4] = *(const uint4*)(kp + (size_t)row*64 + q*8);
        }
        const __nv_bfloat16* vp = g_vT + ((size_t)bh*64)*2048 + j0n;
#pragma unroll
        for (int q4 = 0; q4 < 4; q4++) {
            int idx = q4*256 + tid; int row = idx >> 4, q = idx & 15;
            pvr[q4] = *(const uint4*)(vp + (size_t)row*2048 + q*8);
        }
    };

    float mrow0 = -1e30f, mrow1 = -1e30f, lrow0 = 0.f, lrow1 = 0.f;
    float oacc[8][4] = {};
    const int ia = m0 + r0 + (lane >> 2);         // row A; row B = ia + 8
    const uint32_t* bdr0 = (const uint32_t*)(g_BDs + ((size_t)bh*1024 + ia)*2048) + (lane & 3);
    const uint32_t* bdr1 = (const uint32_t*)(g_BDs + ((size_t)bh*1024 + ia + 8)*2048) + (lane & 3);

    const int ntiles = m0/128 + 9;
    ldg_kv(0);
    for (int jt = 0; jt < ntiles; jt++) {
        const int j0 = jt * 128;
        // ---- STS phase: dump prefetched K/V regs to smem ----
#pragma unroll
        for (int q4 = 0; q4 < 4; q4++) {
            int idx = q4*256 + tid; int row = idx >> 3, q = idx & 7;
            *(uint4*)(smK + row*144 + q*16) = pkr[q4];
        }
#pragma unroll
        for (int q4 = 0; q4 < 4; q4++) {
            int idx = q4*256 + tid; int row = idx >> 4, q = idx & 15;
            *(uint4*)(smV + row*272 + q*16) = pvr[q4];
        }
        __syncthreads();
        if (jt + 1 < ntiles) ldg_kv(jt + 1);

        // ---- S = qu * K^T  (16 rows x 128 cols per warp), ldm feeds MMA directly --
        float sacc[16][4] = {};
#pragma unroll
        for (int ks = 0; ks < 4; ks++) {
#pragma unroll
            for (int nb = 0; nb < 8; nb++) {
                uint32_t t4[4];
                ldm_x4(t4, smK32 + (nb*16 + (lane & 15))*144 + ks*32 + (lane >> 4)*16);
                uint32_t b0[2] = { t4[0], t4[2] };
                uint32_t b1[2] = { t4[1], t4[3] };
                mma16816(sacc[2*nb],   af[ks], b0);
                mma16816(sacc[2*nb+1], af[ks], b1);
            }
        }

        // ---- logits (log2 domain): + shifted BD (direct loads), causal mask ----
        const uint32_t* b0p = bdr0 + (j0 >> 1);
        const uint32_t* b1p = bdr1 + (j0 >> 1);
        float tmax0 = -1e30f, tmax1 = -1e30f;
#pragma unroll
        for (int nf = 0; nf < 16; nf++) {
            int j = j0 + nf*8 + (lane & 3)*2;
            uint32_t bdA = b0p[nf*4];
            uint32_t bdB = b1p[nf*4];
            float a0 = sacc[nf][0] + lo_bf(bdA);
            float a1 = sacc[nf][1] + hi_bf(bdA);
            float b0 = sacc[nf][2] + lo_bf(bdB);
            float b1 = sacc[nf][3] + hi_bf(bdB);
            sacc[nf][0] = (j     <= ia + 1024)     ? a0 : -1e30f;
            sacc[nf][1] = (j + 1 <= ia + 1024)     ? a1 : -1e30f;
            sacc[nf][2] = (j     <= ia + 8 + 1024) ? b0 : -1e30f;
            sacc[nf][3] = (j + 1 <= ia + 8 + 1024) ? b1 : -1e30f;
            tmax0 = fmaxf(tmax0, fmaxf(sacc[nf][0], sacc[nf][1]));
            tmax1 = fmaxf(tmax1, fmaxf(sacc[nf][2], sacc[nf][3]));
        }
        tmax0 = fmaxf(tmax0, __shfl_xor_sync(0xffffffffu, tmax0, 1));
        tmax0 = fmaxf(tmax0, __shfl_xor_sync(0xffffffffu, tmax0, 2));
        tmax1 = fmaxf(tmax1, __shfl_xor_sync(0xffffffffu, tmax1, 1));
        tmax1 = fmaxf(tmax1, __shfl_xor_sync(0xffffffffu, tmax1, 2));

        const float mnew0 = fmaxf(mrow0, tmax0), mnew1 = fmaxf(mrow1, tmax1);
        const float f0 = ex2(mrow0 - mnew0), f1 = ex2(mrow1 - mnew1);
        mrow0 = mnew0; mrow1 = mnew1;
        lrow0 *= f0; lrow1 *= f1;
#pragma unroll
        for (int nf = 0; nf < 8; nf++) {
            oacc[nf][0] *= f0; oacc[nf][1] *= f0;
            oacc[nf][2] *= f1; oacc[nf][3] *= f1;
        }

        // ---- P = 2^(S - m), pack acc frags -> A frags ----
        uint32_t pf[8][4];
        float s0 = 0.f, s1 = 0.f;
#pragma unroll
        for (int kf = 0; kf < 8; kf++) {
            float e00 = ex2(sacc[2*kf][0]   - mnew0), e01 = ex2(sacc[2*kf][1]   - mnew0);
            float e02 = ex2(sacc[2*kf][2]   - mnew1), e03 = ex2(sacc[2*kf][3]   - mnew1);
            float e10 = ex2(sacc[2*kf+1][0] - mnew0), e11 = ex2(sacc[2*kf+1][1] - mnew0);
            float e12 = ex2(sacc[2*kf+1][2] - mnew1), e13 = ex2(sacc[2*kf+1][3] - mnew1);
            s0 += e00 + e01 + e10 + e11;
            s1 += e02 + e03 + e12 + e13;
            pf[kf][0] = pk2(e00, e01);
            pf[kf][1] = pk2(e02, e03);
            pf[kf][2] = pk2(e10, e11);
            pf[kf][3] = pk2(e12, e13);
        }
        lrow0 += s0; lrow1 += s1;

        // ---- O += P * V, ldm feeds MMA directly ----
#pragma unroll
        for (int kf = 0; kf < 8; kf++) {
#pragma unroll
            for (int nb = 0; nb < 4; nb++) {
                uint32_t t4[4];
                ldm_x4(t4, smV32 + (nb*16 + (lane & 15))*272 + kf*32 + (lane >> 4)*16);
                uint32_t b0[2] = { t4[0], t4[2] };
                uint32_t b1[2] = { t4[1], t4[3] };
                mma16816(oacc[2*nb],   pf[kf], b0);
                mma16816(oacc[2*nb+1], pf[kf], b1);
            }
        }
        __syncthreads();
    }

    // ---- finalize: O /= l, write bf16 to g_avec ----
    lrow0 += __shfl_xor_sync(0xffffffffu, lrow0, 1);
    lrow0 += __shfl_xor_sync(0xffffffffu, lrow0, 2);
    lrow1 += __shfl_xor_sync(0xffffffffu, lrow1, 1);
    lrow1 += __shfl_xor_sync(0xffffffffu, lrow1, 2);
    const float inv0 = 1.f / lrow0, inv1 = 1.f / lrow1;

    __nv_bfloat16* d0 = g_avec + ((size_t)ia*4 + b)*1024 + h*64;
    __nv_bfloat16* d1 = g_avec + ((size_t)(ia+8)*4 + b)*1024 + h*64;
#pragma unroll
    for (int nf = 0; nf < 8; nf++) {
        int c = nf*8 + (lane & 3)*2;
        *(uint32_t*)(d0 + c) = pk2(oacc[nf][0]*inv0, oacc[nf][1]*inv0);
        *(uint32_t*)(d1 + c) = pk2(oacc[nf][2]*inv1, oacc[nf][3]*inv1);
    }
}

// ---------------- residual + LayerNorm ------------------------------------------
__global__ void __launch_bounds__(256) ln_kernel(
    const float* __restrict__ x, const float* __restrict__ gamma,
    const float* __restrict__ beta, float* __restrict__ out)
{
    __shared__ float shs[8], shss[8];
    const int n = blockIdx.x;
    const int tid = threadIdx.x;
    const float* xr = x + (size_t)n * DMODEL;
    const float* ar = g_aout + (size_t)n * DMODEL;

    float vals[4];
    float s = 0.f, ss = 0.f;
#pragma unroll
    for (int q = 0; q < 4; q++) {
        int d = tid + q*256;
        float y = xr[d] + ar[d];
        vals[q] = y; s += y; ss += y*y;
    }
#pragma unroll
    for (int o = 16; o > 0; o >>= 1) {
        s  += __shfl_xor_sync(0xffffffffu, s, o);
        ss += __shfl_xor_sync(0xffffffffu, ss, o);
    }
    if ((tid & 31) == 0) { shs[tid>>5] = s; shss[tid>>5] = ss; }
    __syncthreads();
    if (tid < 8) {
        float t1 = shs[tid], t2 = shss[tid];
#pragma unroll
        for (int o = 4; o > 0; o >>= 1) {
            t1 += __shfl_xor_sync(0xffu, t1, o);
            t2 += __shfl_xor_sync(0xffu, t2, o);
        }
        if (tid == 0) { shs[0] = t1; shss[0] = t2; }
    }
    __syncthreads();
    const float mu = shs[0] * (1.0f/DMODEL);
    const float var = shss[0] * (1.0f/DMODEL) - mu*mu;
    const float inv = rsqrtf(var + 1e-5f);

    float* orow = out + (size_t)n * DMODEL;
#pragma unroll
    for (int q = 0; q < 4; q++) {
        int d = tid + q*256;
        orow[d] = (vals[q] - mu) * inv * gamma[d] + beta[d];
    }
}

// ---------------- launch ---------------------------------------------------------
extern "C" void kernel_launch(void* const* d_in, const int* in_sizes, int n_in,
                              void* d_out, int out_size)
{
    (void)in_sizes; (void)n_in; (void)out_size;
    const float* x       = (const float*)d_in[0];
    const float* pos_emb = (const float*)d_in[1];
    const float* bu      = (const float*)d_in[2];
    const float* bv      = (const float*)d_in[3];
    const float* memory  = (const float*)d_in[4];
    const float* W_qkv   = (const float*)d_in[5];
    const float* W_rel   = (const float*)d_in[6];
    const float* W_o     = (const float*)d_in[7];
    const float* gamma   = (const float*)d_in[8];
    const float* beta    = (const float*)d_in[9];
    float* out = (float*)d_out;

    // stage aliased over A/B tiles: dyn smem = max(tiles, stage)
    const int SM_BIG = 69632;   // modes 0,1,5: tiles 2*34816; stage 66048
    const int SM_AB  = 66048;   // mode 3: tiles 2*18432=36864; stage 66048

    cudaFuncSetAttribute(gemm_tc<0>, cudaFuncAttributeMaxDynamicSharedMemorySize, SM_BIG);
    cudaFuncSetAttribute(gemm_tc<1>, cudaFuncAttributeMaxDynamicSharedMemorySize, SM_BIG);
    cudaFuncSetAttribute(gemm_tc<3>, cudaFuncAttributeMaxDynamicSharedMemorySize, SM_AB);
    cudaFuncSetAttribute(gemm_tc<5>, cudaFuncAttributeMaxDynamicSharedMemorySize, SM_BIG);

    // Launch order arranged so QKV is the 4th launch (ncu -s 5 -c 1 captures it,
    // accounting for the 2 harness-internal launches).
    conv_in<<<10240, 256>>>(memory, x, pos_emb);
    transpose_bf<<<dim3(96, 32), 256>>>(W_qkv, 0, 3072);
    transpose_bf<<<dim3(32, 32), 256>>>(W_rel, 1, 1024);
    gemm_tc<0><<<dim3(24, 64),    256, SM_BIG>>>(bu, bv);            // QKV (captured by ncu)
    transpose_bf<<<dim3(32, 32), 256>>>(W_o,   2, 1024);
    gemm_tc<1><<<dim3(8, 16),     256, SM_BIG>>>(nullptr, nullptr);  // REL
    gemm_tc<3><<<dim3(16, 8, 64), 256, SM_AB>>>(nullptr, nullptr);   // BD -> shifted scaled bf16
    flash_attn<<<dim3(8, 64), 256>>>();                              // AC+softmax+PV fused
    gemm_tc<5><<<dim3(8, 32),     256, SM_BIG>>>(nullptr, nullptr);  // OUT
    ln_kernel<<<4096, 256>>>(x, gamma, beta, out);
}